// round 1
// baseline (speedup 1.0000x reference)
#include <cuda_runtime.h>
#include <math.h>

// Problem dims (fixed by the dataset)
#define BB 4
#define NN 4096
#define DD 1024
#define HH 16
#define DH 64
#define FF 4096
#define MM (BB * NN)          // 16384
#define TOT ((size_t)MM * DD) // 16,777,216 elems per [B,N,D] tensor

// ---------------- scratch (static device globals; no allocations) ----------
__device__ float g_q[MM * DD];
__device__ float g_k[MM * DD];
__device__ float g_v[MM * DD];
__device__ float g_attnpre[MM * DD];
__device__ float g_attn[MM * DD];
__device__ float g_h[(size_t)MM * FF];
__device__ float g_out1[MM * DD];
__device__ float g_Gpart[BB * HH * 8 * DH * DH]; // 8 n-splits of Gram partials
__device__ float g_Wt[BB * HH * DH * DH];
__device__ double g_part[4096][2];
__device__ double g_red[2];

// ---------------- fp32 tiled GEMM:  C = A[M,K] * W[N,K]^T + bias (+res)(+gelu)
#define BM 128
#define BN 128
#define BK 8
#define TM 8
#define TN 8

template <bool GELU>
__global__ void __launch_bounds__(256) gemm_kernel(
    const float* __restrict__ A,   // [M,K] row-major
    const float* __restrict__ W,   // [N,K] row-major
    const float* __restrict__ bias,// [N]
    const float* __restrict__ res, // [M,N] or nullptr
    float* __restrict__ C,         // [M,N]
    int M, int N, int K)
{
    __shared__ float As[BK][BM];
    __shared__ float Bs[BK][BN];

    const int tid = threadIdx.x;
    const int bm = blockIdx.y * BM;
    const int bn = blockIdx.x * BN;

    const int ldRow = tid >> 1;        // 0..127
    const int ldCol = (tid & 1) * 4;   // 0 or 4

    const float* Ab = A + (size_t)(bm + ldRow) * K + ldCol;
    const float* Wb = W + (size_t)(bn + ldRow) * K + ldCol;

    float acc[TM][TN];
#pragma unroll
    for (int i = 0; i < TM; i++)
#pragma unroll
        for (int j = 0; j < TN; j++) acc[i][j] = 0.0f;

    const int ty = tid >> 4;  // 0..15
    const int tx = tid & 15;  // 0..15

    for (int k0 = 0; k0 < K; k0 += BK) {
        float4 a4 = *(const float4*)(Ab + k0);
        float4 b4 = *(const float4*)(Wb + k0);
        As[ldCol + 0][ldRow] = a4.x;
        As[ldCol + 1][ldRow] = a4.y;
        As[ldCol + 2][ldRow] = a4.z;
        As[ldCol + 3][ldRow] = a4.w;
        Bs[ldCol + 0][ldRow] = b4.x;
        Bs[ldCol + 1][ldRow] = b4.y;
        Bs[ldCol + 2][ldRow] = b4.z;
        Bs[ldCol + 3][ldRow] = b4.w;
        __syncthreads();

#pragma unroll
        for (int kk = 0; kk < BK; kk++) {
            float ar[TM], br[TN];
#pragma unroll
            for (int i = 0; i < TM; i++) ar[i] = As[kk][ty * TM + i];
#pragma unroll
            for (int j = 0; j < TN; j++) br[j] = Bs[kk][tx * TN + j];
#pragma unroll
            for (int i = 0; i < TM; i++)
#pragma unroll
                for (int j = 0; j < TN; j++) acc[i][j] += ar[i] * br[j];
        }
        __syncthreads();
    }

#pragma unroll
    for (int i = 0; i < TM; i++) {
        const int row = bm + ty * TM + i;
#pragma unroll
        for (int j = 0; j < TN; j++) {
            const int col = bn + tx * TN + j;
            float vv = acc[i][j] + bias[col];
            if (res) vv += res[(size_t)row * N + col];
            if (GELU) vv = 0.5f * vv * (1.0f + erff(vv * 0.70710678118654752f));
            C[(size_t)row * N + col] = vv;
        }
    }
}

// ---------------- Gram: Gpart[bh][ns][i][j] = sum_{n in chunk} q[b,n,h*64+i]*k[b,n,h*64+j]
__global__ void __launch_bounds__(256) gram_kernel(
    const float* __restrict__ q, const float* __restrict__ k,
    float* __restrict__ Gpart)
{
    const int bh = blockIdx.x;      // 0..63
    const int ns = blockIdx.y;      // 0..7
    const int b = bh >> 4, h = bh & 15;
    const int tid = threadIdx.x;
    __shared__ float Qs[32][68];
    __shared__ float Ks[32][68];

    float acc[4][4];
#pragma unroll
    for (int i = 0; i < 4; i++)
#pragma unroll
        for (int j = 0; j < 4; j++) acc[i][j] = 0.0f;

    const int ty = tid >> 4, tx = tid & 15;
    const size_t base = ((size_t)b * NN) * DD + h * DH;
    const int n0s = ns * 512;

    for (int n0 = n0s; n0 < n0s + 512; n0 += 32) {
#pragma unroll
        for (int r = 0; r < 2; r++) {
            int idx4 = tid + r * 256;      // 0..511
            int nn = idx4 >> 4;            // 0..31
            int i4 = (idx4 & 15) * 4;      // 0..60
            float4 qv = *(const float4*)(q + base + (size_t)(n0 + nn) * DD + i4);
            float4 kv = *(const float4*)(k + base + (size_t)(n0 + nn) * DD + i4);
            *(float4*)&Qs[nn][i4] = qv;
            *(float4*)&Ks[nn][i4] = kv;
        }
        __syncthreads();
#pragma unroll
        for (int kk = 0; kk < 32; kk++) {
            float qr[4], kr[4];
#pragma unroll
            for (int i = 0; i < 4; i++) qr[i] = Qs[kk][ty * 4 + i];
#pragma unroll
            for (int j = 0; j < 4; j++) kr[j] = Ks[kk][tx * 4 + j];
#pragma unroll
            for (int i = 0; i < 4; i++)
#pragma unroll
                for (int j = 0; j < 4; j++) acc[i][j] += qr[i] * kr[j];
        }
        __syncthreads();
    }

    float* Gout = Gpart + ((size_t)bh * 8 + ns) * (DH * DH);
#pragma unroll
    for (int i = 0; i < 4; i++)
#pragma unroll
        for (int j = 0; j < 4; j++)
            Gout[(ty * 4 + i) * DH + tx * 4 + j] = acc[i][j];
}

// ---------------- weights[bh][i][j] = | DFT64 over k of G[bh][i][k] at freq j |
__global__ void __launch_bounds__(256) weights_kernel(
    const float* __restrict__ Gpart, float* __restrict__ Wt)
{
    const int bh = blockIdx.x;
    const int tid = threadIdx.x;
    __shared__ float Gs[DH][DH];
    __shared__ float ct[DH], st[DH];

    for (int e = tid; e < DH * DH; e += 256) {
        float s = 0.0f;
#pragma unroll
        for (int p = 0; p < 8; p++)
            s += Gpart[((size_t)bh * 8 + p) * (DH * DH) + e];
        Gs[e >> 6][e & 63] = s;
    }
    if (tid < DH) {
        float a = 6.283185307179586f * (float)tid / 64.0f;
        ct[tid] = cosf(a);
        st[tid] = sinf(a);
    }
    __syncthreads();

    const int i = tid >> 2;
    const int j0 = (tid & 3) * 16;
    for (int jj = 0; jj < 16; jj++) {
        const int j = j0 + jj;
        float re = 0.0f, im = 0.0f;
#pragma unroll
        for (int kk = 0; kk < DH; kk++) {
            const int t = (kk * j) & 63;
            const float g = Gs[i][kk];
            re += g * ct[t];
            im += g * st[t];
        }
        Wt[(size_t)bh * (DH * DH) + i * DH + j] = sqrtf(re * re + im * im);
    }
}

// ---------------- attnpre[b,n,h*64+i] = sum_j weights[bh][i][j] * v[b,n,h*64+j]
__global__ void __launch_bounds__(256) applyw_kernel(
    const float* __restrict__ v, const float* __restrict__ Wt,
    float* __restrict__ out)
{
    const int bh = blockIdx.x;
    const int b = bh >> 4, h = bh & 15;
    const int tid = threadIdx.x;
    __shared__ float Ws[DH][DH + 1];
    __shared__ float Vs[4][DH];

    for (int e = tid; e < DH * DH; e += 256)
        Ws[e >> 6][e & 63] = Wt[(size_t)bh * (DH * DH) + e];
    __syncthreads();

    const int nn = tid >> 6;      // 0..3
    const int i = tid & 63;
    const size_t base = ((size_t)b * NN) * DD + h * DH;
    const int n0 = blockIdx.y * 64;

    for (int n = n0; n < n0 + 64; n += 4) {
        Vs[nn][i] = v[base + (size_t)(n + nn) * DD + i];
        __syncthreads();
        float acc = 0.0f;
#pragma unroll
        for (int j = 0; j < DH; j++) acc += Ws[i][j] * Vs[nn][j];
        out[base + (size_t)(n + nn) * DD + i] = acc;
        __syncthreads();
    }
}

// ---------------- global-std reduction (deterministic, no atomics) -----------
__global__ void __launch_bounds__(256) red1_kernel(const float* __restrict__ x, size_t n)
{
    float s = 0.0f, s2 = 0.0f;
    const size_t stride = (size_t)gridDim.x * blockDim.x;
    for (size_t idx = (size_t)blockIdx.x * blockDim.x + threadIdx.x; idx < n; idx += stride) {
        const float vv = x[idx];
        s += vv;
        s2 += vv * vv;
    }
#pragma unroll
    for (int o = 16; o > 0; o >>= 1) {
        s += __shfl_down_sync(0xFFFFFFFFu, s, o);
        s2 += __shfl_down_sync(0xFFFFFFFFu, s2, o);
    }
    __shared__ double sh[2][8];
    const int w = threadIdx.x >> 5, l = threadIdx.x & 31;
    if (l == 0) { sh[0][w] = (double)s; sh[1][w] = (double)s2; }
    __syncthreads();
    if (threadIdx.x == 0) {
        double a = 0.0, b = 0.0;
#pragma unroll
        for (int i = 0; i < 8; i++) { a += sh[0][i]; b += sh[1][i]; }
        g_part[blockIdx.x][0] = a;
        g_part[blockIdx.x][1] = b;
    }
}

__global__ void __launch_bounds__(256) red2_kernel(int nb)
{
    double a = 0.0, b = 0.0;
    for (int i = threadIdx.x; i < nb; i += 256) { a += g_part[i][0]; b += g_part[i][1]; }
    __shared__ double sa[256], sb[256];
    sa[threadIdx.x] = a;
    sb[threadIdx.x] = b;
    __syncthreads();
    for (int o = 128; o > 0; o >>= 1) {
        if (threadIdx.x < o) { sa[threadIdx.x] += sa[threadIdx.x + o]; sb[threadIdx.x] += sb[threadIdx.x + o]; }
        __syncthreads();
    }
    if (threadIdx.x == 0) { g_red[0] = sa[0]; g_red[1] = sb[0]; }
}

// y = x / (std + eps[d]) * alpha[d] + beta[d],  std = global unbiased std
__global__ void __launch_bounds__(256) norm_kernel(
    const float* __restrict__ x, const float* __restrict__ alpha,
    const float* __restrict__ beta, const float* __restrict__ eps,
    float* __restrict__ y, size_t n)
{
    const double Md = (double)n;
    const double mean = g_red[0] / Md;
    const double var = (g_red[1] - Md * mean * mean) / (Md - 1.0);
    const float sd = (float)sqrt(var);

    const size_t n4 = n >> 2;
    const size_t stride = (size_t)gridDim.x * blockDim.x;
    for (size_t i4 = (size_t)blockIdx.x * blockDim.x + threadIdx.x; i4 < n4; i4 += stride) {
        float4 v = ((const float4*)x)[i4];
        const int d = (int)((i4 * 4) & (DD - 1));
        v.x = v.x / (sd + eps[d + 0]) * alpha[d + 0] + beta[d + 0];
        v.y = v.y / (sd + eps[d + 1]) * alpha[d + 1] + beta[d + 1];
        v.z = v.z / (sd + eps[d + 2]) * alpha[d + 2] + beta[d + 2];
        v.w = v.w / (sd + eps[d + 3]) * alpha[d + 3] + beta[d + 3];
        ((float4*)y)[i4] = v;
    }
}

// ---------------- launch -----------------------------------------------------
extern "C" void kernel_launch(void* const* d_in, const int* in_sizes, int n_in,
                              void* d_out, int out_size)
{
    const float* x      = (const float*)d_in[0];
    const float* wq_w   = (const float*)d_in[1];
    const float* wq_b   = (const float*)d_in[2];
    const float* wk_w   = (const float*)d_in[3];
    const float* wk_b   = (const float*)d_in[4];
    const float* wv_w   = (const float*)d_in[5];
    const float* wv_b   = (const float*)d_in[6];
    const float* wo_w   = (const float*)d_in[7];
    const float* wo_b   = (const float*)d_in[8];
    const float* w1     = (const float*)d_in[9];
    const float* b1     = (const float*)d_in[10];
    const float* w2     = (const float*)d_in[11];
    const float* b2     = (const float*)d_in[12];
    const float* an_a   = (const float*)d_in[13];
    const float* an_b   = (const float*)d_in[14];
    const float* an_e   = (const float*)d_in[15];
    const float* mn_a   = (const float*)d_in[16];
    const float* mn_b   = (const float*)d_in[17];
    const float* mn_e   = (const float*)d_in[18];
    float* out = (float*)d_out;

    float *q, *k, *v, *attnpre, *attn, *hbuf, *out1, *Gpart, *Wt;
    cudaGetSymbolAddress((void**)&q, g_q);
    cudaGetSymbolAddress((void**)&k, g_k);
    cudaGetSymbolAddress((void**)&v, g_v);
    cudaGetSymbolAddress((void**)&attnpre, g_attnpre);
    cudaGetSymbolAddress((void**)&attn, g_attn);
    cudaGetSymbolAddress((void**)&hbuf, g_h);
    cudaGetSymbolAddress((void**)&out1, g_out1);
    cudaGetSymbolAddress((void**)&Gpart, g_Gpart);
    cudaGetSymbolAddress((void**)&Wt, g_Wt);

    const dim3 gProj(DD / BN, MM / BM);   // (8, 128)
    const dim3 gMlp1(FF / BN, MM / BM);   // (32, 128)

    // Q / K / V projections
    gemm_kernel<false><<<gProj, 256>>>(x, wq_w, wq_b, nullptr, q, MM, DD, DD);
    gemm_kernel<false><<<gProj, 256>>>(x, wk_w, wk_b, nullptr, k, MM, DD, DD);
    gemm_kernel<false><<<gProj, 256>>>(x, wv_w, wv_b, nullptr, v, MM, DD, DD);

    // FFT attention, collapsed to Gram -> 64-pt DFT magnitude -> weighted V
    gram_kernel<<<dim3(BB * HH, 8), 256>>>(q, k, Gpart);
    weights_kernel<<<BB * HH, 256>>>(Gpart, Wt);
    applyw_kernel<<<dim3(BB * HH, NN / 64), 256>>>(v, Wt, attnpre);

    // output projection + residual
    gemm_kernel<false><<<gProj, 256>>>(attnpre, wo_w, wo_b, x, attn, MM, DD, DD);

    // rmsnorm 1 (global std), in place
    red1_kernel<<<2048, 256>>>(attn, TOT);
    red2_kernel<<<1, 256>>>(2048);
    norm_kernel<<<2048, 256>>>(attn, an_a, an_b, an_e, attn, TOT);

    // MLP
    gemm_kernel<true><<<gMlp1, 256>>>(attn, w1, b1, nullptr, hbuf, MM, FF, DD);
    gemm_kernel<false><<<gProj, 256>>>(hbuf, w2, b2, attn, out1, MM, DD, FF);

    // rmsnorm 2 -> final output
    red1_kernel<<<2048, 256>>>(out1, TOT);
    red2_kernel<<<1, 256>>>(2048);
    norm_kernel<<<2048, 256>>>(out1, mn_a, mn_b, mn_e, out, TOT);
}

// round 3
// speedup vs baseline: 2.3393x; 2.3393x over previous
#include <cuda_runtime.h>
#include <cuda_bf16.h>
#include <cstdint>
#include <math.h>

// Problem dims (fixed by the dataset)
#define BB 4
#define NN 4096
#define DD 1024
#define HH 16
#define DH 64
#define FF 4096
#define MM (BB * NN)          // 16384
#define TOT ((size_t)MM * DD) // 16,777,216

// ===================== helpers =====================
__device__ __forceinline__ uint32_t smem_u32(const void* p) {
    uint32_t a;
    asm("{ .reg .u64 t; cvta.to.shared.u64 t, %1; cvt.u32.u64 %0, t; }" : "=r"(a) : "l"(p));
    return a;
}
__device__ __forceinline__ void cp_async16(uint32_t dst, const void* src) {
    asm volatile("cp.async.cg.shared.global [%0], [%1], 16;"
                 :: "r"(dst), "l"(__cvta_generic_to_global(src)));
}
__device__ __forceinline__ void cp_commit() { asm volatile("cp.async.commit_group;" ::: "memory"); }
__device__ __forceinline__ void cp_wait0()  { asm volatile("cp.async.wait_group 0;" ::: "memory"); }
__device__ __forceinline__ void cp_wait1()  { asm volatile("cp.async.wait_group 1;" ::: "memory"); }

#define MMA16816(d, a, b0, b1) \
    asm volatile("mma.sync.aligned.m16n8k16.row.col.f32.bf16.bf16.f32 " \
        "{%0,%1,%2,%3}, {%4,%5,%6,%7}, {%8,%9}, {%0,%1,%2,%3};" \
        : "+f"((d)[0]), "+f"((d)[1]), "+f"((d)[2]), "+f"((d)[3]) \
        : "r"((a)[0]), "r"((a)[1]), "r"((a)[2]), "r"((a)[3]), "r"(b0), "r"(b1))

// ===================== scratch (static device globals) =====================
__device__ float g_q[MM * DD];
__device__ float g_k[MM * DD];
__device__ float g_v[MM * DD];
__device__ float g_attnpre[MM * DD];
__device__ float g_attn[MM * DD];
__device__ float g_out1[MM * DD];
__device__ float g_Gpart[BB * HH * 8 * DH * DH];
__device__ float g_Wt[BB * HH * DH * DH];
__device__ double g_part[4096][2];
__device__ double g_red[2];

__device__ __nv_bfloat16 g_xhi[MM * DD],  g_xlo[MM * DD];
__device__ __nv_bfloat16 g_aphi[MM * DD], g_aplo[MM * DD];
__device__ __nv_bfloat16 g_athi[MM * DD], g_atlo[MM * DD];
__device__ __nv_bfloat16 g_hhi[(size_t)MM * FF], g_hlo[(size_t)MM * FF];
__device__ __nv_bfloat16 g_wqhi[DD * DD], g_wqlo[DD * DD];
__device__ __nv_bfloat16 g_wkhi[DD * DD], g_wklo[DD * DD];
__device__ __nv_bfloat16 g_wvhi[DD * DD], g_wvlo[DD * DD];
__device__ __nv_bfloat16 g_wohi[DD * DD], g_wolo[DD * DD];
__device__ __nv_bfloat16 g_w1hi[FF * DD], g_w1lo[FF * DD];
__device__ __nv_bfloat16 g_w2hi[DD * FF], g_w2lo[DD * FF];

// ===================== fp32 -> bf16 hi/lo split =====================
__global__ void __launch_bounds__(256) split_kernel(
    const float* __restrict__ src, __nv_bfloat16* __restrict__ hi,
    __nv_bfloat16* __restrict__ lo, size_t n4)
{
    const size_t stride = (size_t)gridDim.x * blockDim.x;
    for (size_t i4 = (size_t)blockIdx.x * blockDim.x + threadIdx.x; i4 < n4; i4 += stride) {
        float4 v = ((const float4*)src)[i4];
        __nv_bfloat16 h0 = __float2bfloat16(v.x);
        __nv_bfloat16 h1 = __float2bfloat16(v.y);
        __nv_bfloat16 h2 = __float2bfloat16(v.z);
        __nv_bfloat16 h3 = __float2bfloat16(v.w);
        __nv_bfloat162 hA; hA.x = h0; hA.y = h1;
        __nv_bfloat162 hB; hB.x = h2; hB.y = h3;
        __nv_bfloat162 lA; lA.x = __float2bfloat16(v.x - __bfloat162float(h0));
                           lA.y = __float2bfloat16(v.y - __bfloat162float(h1));
        __nv_bfloat162 lB; lB.x = __float2bfloat16(v.z - __bfloat162float(h2));
                           lB.y = __float2bfloat16(v.w - __bfloat162float(h3));
        ((__nv_bfloat162*)hi)[i4 * 2 + 0] = hA;
        ((__nv_bfloat162*)hi)[i4 * 2 + 1] = hB;
        ((__nv_bfloat162*)lo)[i4 * 2 + 0] = lA;
        ((__nv_bfloat162*)lo)[i4 * 2 + 1] = lB;
    }
}

// ===================== HMMA (mma.sync) GEMM =====================
// C[M,N] = A[M,K] * W[N,K]^T + bias (+res)(+gelu), A/W as bf16 hi/lo pairs.
// CTA 128x128, BK=32, 8 warps (4 x 2), warp tile 32x64.
#define GW_BM 128
#define GW_BN 128
#define GW_BK 32
#define ROWB 80                    // padded row pitch (bytes): conflict-free LDS
#define BUFB (128 * ROWB)          // 10240 per buffer (Ahi/Alo/Bhi/Blo)
#define STAGEB (4 * BUFB)          // 40960 per stage
#define GW_SMEM (2 * STAGEB)       // 81920

template <bool HAS_RES, bool GELU, int OUTMODE> // 0: fp32 out; 1: bf16 hi/lo out
__global__ void __launch_bounds__(256) gemm_mma(
    const __nv_bfloat16* __restrict__ Ahi, const __nv_bfloat16* __restrict__ Alo,
    const __nv_bfloat16* __restrict__ Bhi, const __nv_bfloat16* __restrict__ Blo,
    const float* __restrict__ bias, const float* __restrict__ res,
    float* __restrict__ Cf, __nv_bfloat16* __restrict__ Chi, __nv_bfloat16* __restrict__ Clo,
    int M, int N, int K)
{
    extern __shared__ char sm[];
    const int tid = threadIdx.x;
    const int wid = tid >> 5;
    const int lane = tid & 31;
    const int wm = wid & 3;        // 0..3 (M)
    const int wn = wid >> 2;       // 0..1 (N)
    const int bm = blockIdx.y * GW_BM;
    const int bn = blockIdx.x * GW_BN;
    const int KT = K / GW_BK;

    auto load_stage = [&](int kt, char* sb) {
        const int k0 = kt * GW_BK;
#pragma unroll
        for (int i = 0; i < 8; i++) {
            const int c = tid + i * 256;      // 0..2047
            const int buf = c >> 9;           // 0:Ahi 1:Alo 2:Bhi 3:Blo
            const int cc = c & 511;
            const int row = cc >> 2;          // 0..127
            const int qq = cc & 3;            // 16B chunk in row
            const __nv_bfloat16* gb = (buf == 0) ? Ahi : (buf == 1) ? Alo
                                     : (buf == 2) ? Bhi : Blo;
            const int grow = ((buf < 2) ? bm : bn) + row;
            const void* src = gb + (size_t)grow * K + k0 + qq * 8;
            cp_async16(smem_u32(sb + buf * BUFB + row * ROWB + qq * 16), src);
        }
    };

    float acc[2][8][4];
#pragma unroll
    for (int mt = 0; mt < 2; mt++)
#pragma unroll
        for (int nt = 0; nt < 8; nt++)
#pragma unroll
            for (int r = 0; r < 4; r++) acc[mt][nt][r] = 0.0f;

    load_stage(0, sm);
    cp_commit();

    const int arow = wm * 32 + (lane >> 2);
    const int kb = (lane & 3) * 4;

    for (int kt = 0; kt < KT; kt++) {
        char* sb = sm + (kt & 1) * STAGEB;
        if (kt + 1 < KT) {
            load_stage(kt + 1, sm + ((kt + 1) & 1) * STAGEB);
            cp_commit();
            cp_wait1();
        } else {
            cp_wait0();
        }
        __syncthreads();

        const char* As = sb;               // Ahi @0, Alo @BUFB
        const char* Bs = sb + 2 * BUFB;    // Bhi @0, Blo @BUFB

#pragma unroll
        for (int k16 = 0; k16 < 2; k16++) {
            const int kbb = kb + k16 * 32;  // byte offset of this k16 chunk
            uint32_t ah[2][4], al[2][4];
#pragma unroll
            for (int mt = 0; mt < 2; mt++) {
                const char* p = As + (arow + mt * 16) * ROWB + kbb;
                ah[mt][0] = *(const uint32_t*)(p);
                ah[mt][1] = *(const uint32_t*)(p + 8 * ROWB);
                ah[mt][2] = *(const uint32_t*)(p + 16);
                ah[mt][3] = *(const uint32_t*)(p + 8 * ROWB + 16);
                const char* pl = p + BUFB;
                al[mt][0] = *(const uint32_t*)(pl);
                al[mt][1] = *(const uint32_t*)(pl + 8 * ROWB);
                al[mt][2] = *(const uint32_t*)(pl + 16);
                al[mt][3] = *(const uint32_t*)(pl + 8 * ROWB + 16);
            }
#pragma unroll
            for (int nt = 0; nt < 8; nt++) {
                const int bcol = wn * 64 + nt * 8 + (lane >> 2);
                const char* pb = Bs + bcol * ROWB + kbb;
                const uint32_t bh0 = *(const uint32_t*)(pb);
                const uint32_t bh1 = *(const uint32_t*)(pb + 16);
                const uint32_t bl0 = *(const uint32_t*)(pb + BUFB);
                const uint32_t bl1 = *(const uint32_t*)(pb + BUFB + 16);
#pragma unroll
                for (int mt = 0; mt < 2; mt++) {
                    MMA16816(acc[mt][nt], ah[mt], bh0, bh1);
                    MMA16816(acc[mt][nt], ah[mt], bl0, bl1);
                    MMA16816(acc[mt][nt], al[mt], bh0, bh1);
                }
            }
        }
        __syncthreads();
    }

    // ---- epilogue (register-resident) ----
#pragma unroll
    for (int mt = 0; mt < 2; mt++) {
        const int r0 = bm + wm * 32 + mt * 16 + (lane >> 2);
#pragma unroll
        for (int nt = 0; nt < 8; nt++) {
            const int c = bn + wn * 64 + nt * 8 + ((lane & 3) << 1);
            const float b0 = bias[c], b1 = bias[c + 1];
#pragma unroll
            for (int half = 0; half < 2; half++) {
                const int row = r0 + half * 8;
                float v0 = acc[mt][nt][half * 2 + 0] + b0;
                float v1 = acc[mt][nt][half * 2 + 1] + b1;
                if (HAS_RES) {
                    const float2 rr = *(const float2*)(res + (size_t)row * N + c);
                    v0 += rr.x; v1 += rr.y;
                }
                if (GELU) {
                    v0 = 0.5f * v0 * (1.0f + erff(v0 * 0.70710678118654752f));
                    v1 = 0.5f * v1 * (1.0f + erff(v1 * 0.70710678118654752f));
                }
                if (OUTMODE == 0) {
                    float2 o; o.x = v0; o.y = v1;
                    *(float2*)(Cf + (size_t)row * N + c) = o;
                } else {
                    __nv_bfloat162 h, l;
                    h.x = __float2bfloat16(v0);
                    h.y = __float2bfloat16(v1);
                    l.x = __float2bfloat16(v0 - __bfloat162float(h.x));
                    l.y = __float2bfloat16(v1 - __bfloat162float(h.y));
                    *(__nv_bfloat162*)(Chi + (size_t)row * N + c) = h;
                    *(__nv_bfloat162*)(Clo + (size_t)row * N + c) = l;
                }
            }
        }
    }
}

// ===================== attention small ops =====================
__global__ void __launch_bounds__(256) gram_kernel(
    const float* __restrict__ q, const float* __restrict__ k,
    float* __restrict__ Gpart)
{
    const int bh = blockIdx.x;
    const int ns = blockIdx.y;
    const int b = bh >> 4, h = bh & 15;
    const int tid = threadIdx.x;
    __shared__ float Qs[32][68];
    __shared__ float Ks[32][68];

    float acc[4][4];
#pragma unroll
    for (int i = 0; i < 4; i++)
#pragma unroll
        for (int j = 0; j < 4; j++) acc[i][j] = 0.0f;

    const int ty = tid >> 4, tx = tid & 15;
    const size_t base = ((size_t)b * NN) * DD + h * DH;
    const int n0s = ns * 512;

    for (int n0 = n0s; n0 < n0s + 512; n0 += 32) {
#pragma unroll
        for (int r = 0; r < 2; r++) {
            int idx4 = tid + r * 256;
            int nn = idx4 >> 4;
            int i4 = (idx4 & 15) * 4;
            float4 qv = *(const float4*)(q + base + (size_t)(n0 + nn) * DD + i4);
            float4 kv = *(const float4*)(k + base + (size_t)(n0 + nn) * DD + i4);
            *(float4*)&Qs[nn][i4] = qv;
            *(float4*)&Ks[nn][i4] = kv;
        }
        __syncthreads();
#pragma unroll
        for (int kk = 0; kk < 32; kk++) {
            float qr[4], kr[4];
#pragma unroll
            for (int i = 0; i < 4; i++) qr[i] = Qs[kk][ty * 4 + i];
#pragma unroll
            for (int j = 0; j < 4; j++) kr[j] = Ks[kk][tx * 4 + j];
#pragma unroll
            for (int i = 0; i < 4; i++)
#pragma unroll
                for (int j = 0; j < 4; j++) acc[i][j] += qr[i] * kr[j];
        }
        __syncthreads();
    }

    float* Gout = Gpart + ((size_t)bh * 8 + ns) * (DH * DH);
#pragma unroll
    for (int i = 0; i < 4; i++)
#pragma unroll
        for (int j = 0; j < 4; j++)
            Gout[(ty * 4 + i) * DH + tx * 4 + j] = acc[i][j];
}

__global__ void __launch_bounds__(256) weights_kernel(
    const float* __restrict__ Gpart, float* __restrict__ Wt)
{
    const int bh = blockIdx.x;
    const int tid = threadIdx.x;
    __shared__ float Gs[DH][DH];
    __shared__ float ct[DH], st[DH];

    for (int e = tid; e < DH * DH; e += 256) {
        float s = 0.0f;
#pragma unroll
        for (int p = 0; p < 8; p++)
            s += Gpart[((size_t)bh * 8 + p) * (DH * DH) + e];
        Gs[e >> 6][e & 63] = s;
    }
    if (tid < DH) {
        float a = 6.283185307179586f * (float)tid / 64.0f;
        ct[tid] = cosf(a);
        st[tid] = sinf(a);
    }
    __syncthreads();

    const int i = tid >> 2;
    const int j0 = (tid & 3) * 16;
    for (int jj = 0; jj < 16; jj++) {
        const int j = j0 + jj;
        float re = 0.0f, im = 0.0f;
#pragma unroll
        for (int kk = 0; kk < DH; kk++) {
            const int t = (kk * j) & 63;
            const float g = Gs[i][kk];
            re += g * ct[t];
            im += g * st[t];
        }
        Wt[(size_t)bh * (DH * DH) + i * DH + j] = sqrtf(re * re + im * im);
    }
}

__global__ void __launch_bounds__(256) applyw_kernel(
    const float* __restrict__ v, const float* __restrict__ Wt,
    float* __restrict__ out)
{
    const int bh = blockIdx.x;
    const int b = bh >> 4, h = bh & 15;
    const int tid = threadIdx.x;
    __shared__ float Ws[DH][DH + 1];
    __shared__ float Vs[4][DH];

    for (int e = tid; e < DH * DH; e += 256)
        Ws[e >> 6][e & 63] = Wt[(size_t)bh * (DH * DH) + e];
    __syncthreads();

    const int nn = tid >> 6;
    const int i = tid & 63;
    const size_t base = ((size_t)b * NN) * DD + h * DH;
    const int n0 = blockIdx.y * 64;

    for (int n = n0; n < n0 + 64; n += 4) {
        Vs[nn][i] = v[base + (size_t)(n + nn) * DD + i];
        __syncthreads();
        float acc = 0.0f;
#pragma unroll
        for (int j = 0; j < DH; j++) acc += Ws[i][j] * Vs[nn][j];
        out[base + (size_t)(n + nn) * DD + i] = acc;
        __syncthreads();
    }
}

// ===================== global-std reduction + norm =====================
__global__ void __launch_bounds__(256) red1_kernel(const float* __restrict__ x, size_t n)
{
    float s = 0.0f, s2 = 0.0f;
    const size_t stride = (size_t)gridDim.x * blockDim.x;
    for (size_t idx = (size_t)blockIdx.x * blockDim.x + threadIdx.x; idx < n; idx += stride) {
        const float vv = x[idx];
        s += vv;
        s2 += vv * vv;
    }
#pragma unroll
    for (int o = 16; o > 0; o >>= 1) {
        s += __shfl_down_sync(0xFFFFFFFFu, s, o);
        s2 += __shfl_down_sync(0xFFFFFFFFu, s2, o);
    }
    __shared__ double sh[2][8];
    const int w = threadIdx.x >> 5, l = threadIdx.x & 31;
    if (l == 0) { sh[0][w] = (double)s; sh[1][w] = (double)s2; }
    __syncthreads();
    if (threadIdx.x == 0) {
        double a = 0.0, b = 0.0;
#pragma unroll
        for (int i = 0; i < 8; i++) { a += sh[0][i]; b += sh[1][i]; }
        g_part[blockIdx.x][0] = a;
        g_part[blockIdx.x][1] = b;
    }
}

__global__ void __launch_bounds__(256) red2_kernel(int nb)
{
    double a = 0.0, b = 0.0;
    for (int i = threadIdx.x; i < nb; i += 256) { a += g_part[i][0]; b += g_part[i][1]; }
    __shared__ double sa[256], sb[256];
    sa[threadIdx.x] = a;
    sb[threadIdx.x] = b;
    __syncthreads();
    for (int o = 128; o > 0; o >>= 1) {
        if (threadIdx.x < o) { sa[threadIdx.x] += sa[threadIdx.x + o]; sb[threadIdx.x] += sb[threadIdx.x + o]; }
        __syncthreads();
    }
    if (threadIdx.x == 0) { g_red[0] = sa[0]; g_red[1] = sb[0]; }
}

template <bool SPLIT>
__global__ void __launch_bounds__(256) norm_kernel(
    const float* __restrict__ x, const float* __restrict__ alpha,
    const float* __restrict__ beta, const float* __restrict__ eps,
    float* __restrict__ y, __nv_bfloat16* __restrict__ yhi,
    __nv_bfloat16* __restrict__ ylo, size_t n)
{
    const double Md = (double)n;
    const double mean = g_red[0] / Md;
    const double var = (g_red[1] - Md * mean * mean) / (Md - 1.0);
    const float sd = (float)sqrt(var);

    const size_t n4 = n >> 2;
    const size_t stride = (size_t)gridDim.x * blockDim.x;
    for (size_t i4 = (size_t)blockIdx.x * blockDim.x + threadIdx.x; i4 < n4; i4 += stride) {
        float4 v = ((const float4*)x)[i4];
        const int d = (int)((i4 * 4) & (DD - 1));
        v.x = v.x / (sd + eps[d + 0]) * alpha[d + 0] + beta[d + 0];
        v.y = v.y / (sd + eps[d + 1]) * alpha[d + 1] + beta[d + 1];
        v.z = v.z / (sd + eps[d + 2]) * alpha[d + 2] + beta[d + 2];
        v.w = v.w / (sd + eps[d + 3]) * alpha[d + 3] + beta[d + 3];
        ((float4*)y)[i4] = v;
        if (SPLIT) {
            __nv_bfloat16 h0 = __float2bfloat16(v.x);
            __nv_bfloat16 h1 = __float2bfloat16(v.y);
            __nv_bfloat16 h2 = __float2bfloat16(v.z);
            __nv_bfloat16 h3 = __float2bfloat16(v.w);
            __nv_bfloat162 hA; hA.x = h0; hA.y = h1;
            __nv_bfloat162 hB; hB.x = h2; hB.y = h3;
            __nv_bfloat162 lA; lA.x = __float2bfloat16(v.x - __bfloat162float(h0));
                               lA.y = __float2bfloat16(v.y - __bfloat162float(h1));
            __nv_bfloat162 lB; lB.x = __float2bfloat16(v.z - __bfloat162float(h2));
                               lB.y = __float2bfloat16(v.w - __bfloat162float(h3));
            ((__nv_bfloat162*)yhi)[i4 * 2 + 0] = hA;
            ((__nv_bfloat162*)yhi)[i4 * 2 + 1] = hB;
            ((__nv_bfloat162*)ylo)[i4 * 2 + 0] = lA;
            ((__nv_bfloat162*)ylo)[i4 * 2 + 1] = lB;
        }
    }
}

// ===================== launch =====================
extern "C" void kernel_launch(void* const* d_in, const int* in_sizes, int n_in,
                              void* d_out, int out_size)
{
    const float* x    = (const float*)d_in[0];
    const float* wq_w = (const float*)d_in[1];
    const float* wq_b = (const float*)d_in[2];
    const float* wk_w = (const float*)d_in[3];
    const float* wk_b = (const float*)d_in[4];
    const float* wv_w = (const float*)d_in[5];
    const float* wv_b = (const float*)d_in[6];
    const float* wo_w = (const float*)d_in[7];
    const float* wo_b = (const float*)d_in[8];
    const float* w1   = (const float*)d_in[9];
    const float* b1   = (const float*)d_in[10];
    const float* w2   = (const float*)d_in[11];
    const float* b2   = (const float*)d_in[12];
    const float* an_a = (const float*)d_in[13];
    const float* an_b = (const float*)d_in[14];
    const float* an_e = (const float*)d_in[15];
    const float* mn_a = (const float*)d_in[16];
    const float* mn_b = (const float*)d_in[17];
    const float* mn_e = (const float*)d_in[18];
    float* out = (float*)d_out;

    float *q, *k, *v, *attnpre, *attn, *out1, *Gpart, *Wt;
    cudaGetSymbolAddress((void**)&q, g_q);
    cudaGetSymbolAddress((void**)&k, g_k);
    cudaGetSymbolAddress((void**)&v, g_v);
    cudaGetSymbolAddress((void**)&attnpre, g_attnpre);
    cudaGetSymbolAddress((void**)&attn, g_attn);
    cudaGetSymbolAddress((void**)&out1, g_out1);
    cudaGetSymbolAddress((void**)&Gpart, g_Gpart);
    cudaGetSymbolAddress((void**)&Wt, g_Wt);

    __nv_bfloat16 *xhi, *xlo, *aphi, *aplo, *athi, *atlo, *hhi, *hlo;
    __nv_bfloat16 *wqh, *wql, *wkh, *wkl, *wvh, *wvl, *woh, *wol, *w1h, *w1l, *w2h, *w2l;
    cudaGetSymbolAddress((void**)&xhi, g_xhi);   cudaGetSymbolAddress((void**)&xlo, g_xlo);
    cudaGetSymbolAddress((void**)&aphi, g_aphi); cudaGetSymbolAddress((void**)&aplo, g_aplo);
    cudaGetSymbolAddress((void**)&athi, g_athi); cudaGetSymbolAddress((void**)&atlo, g_atlo);
    cudaGetSymbolAddress((void**)&hhi, g_hhi);   cudaGetSymbolAddress((void**)&hlo, g_hlo);
    cudaGetSymbolAddress((void**)&wqh, g_wqhi);  cudaGetSymbolAddress((void**)&wql, g_wqlo);
    cudaGetSymbolAddress((void**)&wkh, g_wkhi);  cudaGetSymbolAddress((void**)&wkl, g_wklo);
    cudaGetSymbolAddress((void**)&wvh, g_wvhi);  cudaGetSymbolAddress((void**)&wvl, g_wvlo);
    cudaGetSymbolAddress((void**)&woh, g_wohi);  cudaGetSymbolAddress((void**)&wol, g_wolo);
    cudaGetSymbolAddress((void**)&w1h, g_w1hi);  cudaGetSymbolAddress((void**)&w1l, g_w1lo);
    cudaGetSymbolAddress((void**)&w2h, g_w2hi);  cudaGetSymbolAddress((void**)&w2l, g_w2lo);

    cudaFuncSetAttribute(gemm_mma<false, false, 0>, cudaFuncAttributeMaxDynamicSharedMemorySize, GW_SMEM);
    cudaFuncSetAttribute(gemm_mma<true,  false, 0>, cudaFuncAttributeMaxDynamicSharedMemorySize, GW_SMEM);
    cudaFuncSetAttribute(gemm_mma<false, true,  1>, cudaFuncAttributeMaxDynamicSharedMemorySize, GW_SMEM);

    // ---- convert inputs to bf16 hi/lo ----
    split_kernel<<<1024, 256>>>(x, xhi, xlo, TOT / 4);
    split_kernel<<<256, 256>>>(wq_w, wqh, wql, (size_t)DD * DD / 4);
    split_kernel<<<256, 256>>>(wk_w, wkh, wkl, (size_t)DD * DD / 4);
    split_kernel<<<256, 256>>>(wv_w, wvh, wvl, (size_t)DD * DD / 4);
    split_kernel<<<256, 256>>>(wo_w, woh, wol, (size_t)DD * DD / 4);
    split_kernel<<<512, 256>>>(w1, w1h, w1l, (size_t)FF * DD / 4);
    split_kernel<<<512, 256>>>(w2, w2h, w2l, (size_t)DD * FF / 4);

    const dim3 gProj(DD / GW_BN, MM / GW_BM);   // (8, 128)
    const dim3 gMlp1(FF / GW_BN, MM / GW_BM);   // (32, 128)

    // ---- Q/K/V projections ----
    gemm_mma<false, false, 0><<<gProj, 256, GW_SMEM>>>(xhi, xlo, wqh, wql, wq_b, nullptr, q, nullptr, nullptr, MM, DD, DD);
    gemm_mma<false, false, 0><<<gProj, 256, GW_SMEM>>>(xhi, xlo, wkh, wkl, wk_b, nullptr, k, nullptr, nullptr, MM, DD, DD);
    gemm_mma<false, false, 0><<<gProj, 256, GW_SMEM>>>(xhi, xlo, wvh, wvl, wv_b, nullptr, v, nullptr, nullptr, MM, DD, DD);

    // ---- FFT attention (collapsed form) ----
    gram_kernel<<<dim3(BB * HH, 8), 256>>>(q, k, Gpart);
    weights_kernel<<<BB * HH, 256>>>(Gpart, Wt);
    applyw_kernel<<<dim3(BB * HH, NN / 64), 256>>>(v, Wt, attnpre);

    // ---- output projection + residual ----
    split_kernel<<<1024, 256>>>(attnpre, aphi, aplo, TOT / 4);
    gemm_mma<true, false, 0><<<gProj, 256, GW_SMEM>>>(aphi, aplo, woh, wol, wo_b, x, attn, nullptr, nullptr, MM, DD, DD);

    // ---- rmsnorm 1 (global std), also emits bf16 hi/lo for MLP1 ----
    red1_kernel<<<2048, 256>>>(attn, TOT);
    red2_kernel<<<1, 256>>>(2048);
    norm_kernel<true><<<2048, 256>>>(attn, an_a, an_b, an_e, attn, athi, atlo, TOT);

    // ---- MLP ----
    gemm_mma<false, true, 1><<<gMlp1, 256, GW_SMEM>>>(athi, atlo, w1h, w1l, b1, nullptr, nullptr, hhi, hlo, MM, FF, DD);
    gemm_mma<true, false, 0><<<gProj, 256, GW_SMEM>>>(hhi, hlo, w2h, w2l, b2, attn, out1, nullptr, nullptr, MM, DD, FF);

    // ---- rmsnorm 2 -> final output ----
    red1_kernel<<<2048, 256>>>(out1, TOT);
    red2_kernel<<<1, 256>>>(2048);
    norm_kernel<false><<<2048, 256>>>(out1, mn_a, mn_b, mn_e, out, nullptr, nullptr, TOT);
}

// round 4
// speedup vs baseline: 2.8196x; 1.2053x over previous
#include <cuda_runtime.h>
#include <cuda_bf16.h>
#include <cstdint>
#include <math.h>

// Problem dims (fixed by the dataset)
#define BB 4
#define NN 4096
#define DD 1024
#define HH 16
#define DH 64
#define FF 4096
#define MM (BB * NN)          // 16384
#define TOT ((size_t)MM * DD) // 16,777,216

// ===================== helpers =====================
__device__ __forceinline__ uint32_t smem_u32(const void* p) {
    uint32_t a;
    asm("{ .reg .u64 t; cvta.to.shared.u64 t, %1; cvt.u32.u64 %0, t; }" : "=r"(a) : "l"(p));
    return a;
}
__device__ __forceinline__ void cp_async16(uint32_t dst, const void* src) {
    asm volatile("cp.async.cg.shared.global [%0], [%1], 16;"
                 :: "r"(dst), "l"(__cvta_generic_to_global(src)));
}
__device__ __forceinline__ void cp_commit() { asm volatile("cp.async.commit_group;" ::: "memory"); }
__device__ __forceinline__ void cp_wait0()  { asm volatile("cp.async.wait_group 0;" ::: "memory"); }
__device__ __forceinline__ void cp_wait1()  { asm volatile("cp.async.wait_group 1;" ::: "memory"); }

#define MMA16816(d, a, b0, b1) \
    asm volatile("mma.sync.aligned.m16n8k16.row.col.f32.bf16.bf16.f32 " \
        "{%0,%1,%2,%3}, {%4,%5,%6,%7}, {%8,%9}, {%0,%1,%2,%3};" \
        : "+f"((d)[0]), "+f"((d)[1]), "+f"((d)[2]), "+f"((d)[3]) \
        : "r"((a)[0]), "r"((a)[1]), "r"((a)[2]), "r"((a)[3]), "r"(b0), "r"(b1))

#define LDMX4(r, addr) \
    asm volatile("ldmatrix.sync.aligned.m8n8.x4.shared.b16 {%0,%1,%2,%3}, [%4];" \
        : "=r"((r)[0]), "=r"((r)[1]), "=r"((r)[2]), "=r"((r)[3]) : "r"(addr))

// ===================== scratch (static device globals) =====================
__device__ float g_q[MM * DD];
__device__ float g_k[MM * DD];
__device__ float g_v[MM * DD];
__device__ float g_attn[MM * DD];
__device__ float g_out1[MM * DD];
__device__ float g_Gpart[BB * HH * 8 * DH * DH];
__device__ float g_Wt[BB * HH * DH * DH];
__device__ double g_part[4096][2];
__device__ double g_red[2];

__device__ __nv_bfloat16 g_xhi[MM * DD],  g_xlo[MM * DD];
__device__ __nv_bfloat16 g_aphi[MM * DD], g_aplo[MM * DD];
__device__ __nv_bfloat16 g_athi[MM * DD], g_atlo[MM * DD];
__device__ __nv_bfloat16 g_hhi[(size_t)MM * FF], g_hlo[(size_t)MM * FF];
__device__ __nv_bfloat16 g_wqhi[DD * DD], g_wqlo[DD * DD];
__device__ __nv_bfloat16 g_wkhi[DD * DD], g_wklo[DD * DD];
__device__ __nv_bfloat16 g_wvhi[DD * DD], g_wvlo[DD * DD];
__device__ __nv_bfloat16 g_wohi[DD * DD], g_wolo[DD * DD];
__device__ __nv_bfloat16 g_w1hi[FF * DD], g_w1lo[FF * DD];
__device__ __nv_bfloat16 g_w2hi[DD * FF], g_w2lo[DD * FF];

// ===================== fp32 -> bf16 hi/lo split =====================
__global__ void __launch_bounds__(256) split_kernel(
    const float* __restrict__ src, __nv_bfloat16* __restrict__ hi,
    __nv_bfloat16* __restrict__ lo, size_t n4)
{
    const size_t stride = (size_t)gridDim.x * blockDim.x;
    for (size_t i4 = (size_t)blockIdx.x * blockDim.x + threadIdx.x; i4 < n4; i4 += stride) {
        float4 v = ((const float4*)src)[i4];
        __nv_bfloat16 h0 = __float2bfloat16(v.x);
        __nv_bfloat16 h1 = __float2bfloat16(v.y);
        __nv_bfloat16 h2 = __float2bfloat16(v.z);
        __nv_bfloat16 h3 = __float2bfloat16(v.w);
        __nv_bfloat162 hA; hA.x = h0; hA.y = h1;
        __nv_bfloat162 hB; hB.x = h2; hB.y = h3;
        __nv_bfloat162 lA; lA.x = __float2bfloat16(v.x - __bfloat162float(h0));
                           lA.y = __float2bfloat16(v.y - __bfloat162float(h1));
        __nv_bfloat162 lB; lB.x = __float2bfloat16(v.z - __bfloat162float(h2));
                           lB.y = __float2bfloat16(v.w - __bfloat162float(h3));
        ((__nv_bfloat162*)hi)[i4 * 2 + 0] = hA;
        ((__nv_bfloat162*)hi)[i4 * 2 + 1] = hB;
        ((__nv_bfloat162*)lo)[i4 * 2 + 0] = lA;
        ((__nv_bfloat162*)lo)[i4 * 2 + 1] = lB;
    }
}

// ===================== HMMA (mma.sync + ldmatrix) GEMM =====================
// C[M,N] = A[M,K] * W[N,K]^T + bias (+res)(+gelu), A/W as bf16 hi/lo pairs.
// CTA 128x128, BK=32, 8 warps (4 x 2), warp tile 32x64.
#define GW_BM 128
#define GW_BN 128
#define GW_BK 32
#define ROWB 80                    // padded row pitch (bytes): conflict-free ldmatrix
#define BUFB (128 * ROWB)          // 10240 per buffer (Ahi/Alo/Bhi/Blo)
#define STAGEB (4 * BUFB)          // 40960 per stage
#define GW_SMEM (2 * STAGEB)       // 81920

template <bool HAS_RES, bool GELU, int OUTMODE> // 0: fp32 out; 1: bf16 hi/lo out
__global__ void __launch_bounds__(256, 2) gemm_mma(
    const __nv_bfloat16* __restrict__ Ahi, const __nv_bfloat16* __restrict__ Alo,
    const __nv_bfloat16* __restrict__ Bhi, const __nv_bfloat16* __restrict__ Blo,
    const float* __restrict__ bias, const float* __restrict__ res,
    float* __restrict__ Cf, __nv_bfloat16* __restrict__ Chi, __nv_bfloat16* __restrict__ Clo,
    int M, int N, int K)
{
    extern __shared__ char sm[];
    const int tid = threadIdx.x;
    const int wid = tid >> 5;
    const int lane = tid & 31;
    const int wm = wid & 3;        // 0..3 (M)
    const int wn = wid >> 2;       // 0..1 (N)
    const int bm = blockIdx.y * GW_BM;
    const int bn = blockIdx.x * GW_BN;
    const int KT = K / GW_BK;
    const uint32_t smb = smem_u32(sm);

    auto load_stage = [&](int kt, uint32_t sb) {
        const int k0 = kt * GW_BK;
#pragma unroll
        for (int i = 0; i < 8; i++) {
            const int c = tid + i * 256;      // 0..2047
            const int buf = c >> 9;           // 0:Ahi 1:Alo 2:Bhi 3:Blo
            const int cc = c & 511;
            const int row = cc >> 2;          // 0..127
            const int qq = cc & 3;            // 16B chunk in row
            const __nv_bfloat16* gb = (buf == 0) ? Ahi : (buf == 1) ? Alo
                                     : (buf == 2) ? Bhi : Blo;
            const int grow = ((buf < 2) ? bm : bn) + row;
            const void* src = gb + (size_t)grow * K + k0 + qq * 8;
            cp_async16(sb + buf * BUFB + row * ROWB + qq * 16, src);
        }
    };

    float acc[2][8][4];
#pragma unroll
    for (int mt = 0; mt < 2; mt++)
#pragma unroll
        for (int nt = 0; nt < 8; nt++)
#pragma unroll
            for (int r = 0; r < 4; r++) acc[mt][nt][r] = 0.0f;

    load_stage(0, smb);
    cp_commit();

    // ldmatrix per-lane addressing offsets
    const int lr = lane & 7;
    const int a_row = wm * 32 + lr + ((lane & 8) ? 8 : 0);
    const int a_kb  = (lane & 16) ? 16 : 0;
    const int b_row = wn * 64 + lr + ((lane & 16) ? 8 : 0);
    const int b_kb  = (lane & 8) ? 16 : 0;

    for (int kt = 0; kt < KT; kt++) {
        const uint32_t sb = smb + (uint32_t)(kt & 1) * STAGEB;
        if (kt + 1 < KT) {
            load_stage(kt + 1, smb + (uint32_t)((kt + 1) & 1) * STAGEB);
            cp_commit();
            cp_wait1();
        } else {
            cp_wait0();
        }
        __syncthreads();

        const uint32_t As = sb;               // Ahi @0, Alo @BUFB
        const uint32_t Bs = sb + 2 * BUFB;    // Bhi @0, Blo @BUFB

#pragma unroll
        for (int k16 = 0; k16 < 2; k16++) {
            const int kc = k16 * 32;
            uint32_t ah[2][4], al[2][4];
#pragma unroll
            for (int mt = 0; mt < 2; mt++) {
                const uint32_t aAddr = As + (uint32_t)((a_row + mt * 16) * ROWB + kc + a_kb);
                LDMX4(ah[mt], aAddr);
                LDMX4(al[mt], aAddr + BUFB);
            }
#pragma unroll
            for (int p = 0; p < 4; p++) {
                uint32_t bh[4], bl[4];
                const uint32_t bAddr = Bs + (uint32_t)((b_row + p * 16) * ROWB + kc + b_kb);
                LDMX4(bh, bAddr);
                LDMX4(bl, bAddr + BUFB);
#pragma unroll
                for (int sub = 0; sub < 2; sub++) {
                    const int nt = p * 2 + sub;
                    const uint32_t b0h = bh[sub * 2], b1h = bh[sub * 2 + 1];
                    const uint32_t b0l = bl[sub * 2], b1l = bl[sub * 2 + 1];
#pragma unroll
                    for (int mt = 0; mt < 2; mt++) {
                        MMA16816(acc[mt][nt], ah[mt], b0h, b1h);
                        MMA16816(acc[mt][nt], ah[mt], b0l, b1l);
                        MMA16816(acc[mt][nt], al[mt], b0h, b1h);
                    }
                }
            }
        }
        __syncthreads();
    }

    // ---- epilogue (register-resident) ----
#pragma unroll
    for (int mt = 0; mt < 2; mt++) {
        const int r0 = bm + wm * 32 + mt * 16 + (lane >> 2);
#pragma unroll
        for (int nt = 0; nt < 8; nt++) {
            const int c = bn + wn * 64 + nt * 8 + ((lane & 3) << 1);
            const float b0 = bias[c], b1 = bias[c + 1];
#pragma unroll
            for (int half = 0; half < 2; half++) {
                const int row = r0 + half * 8;
                float v0 = acc[mt][nt][half * 2 + 0] + b0;
                float v1 = acc[mt][nt][half * 2 + 1] + b1;
                if (HAS_RES) {
                    const float2 rr = *(const float2*)(res + (size_t)row * N + c);
                    v0 += rr.x; v1 += rr.y;
                }
                if (GELU) {
                    v0 = 0.5f * v0 * (1.0f + erff(v0 * 0.70710678118654752f));
                    v1 = 0.5f * v1 * (1.0f + erff(v1 * 0.70710678118654752f));
                }
                if (OUTMODE == 0) {
                    float2 o; o.x = v0; o.y = v1;
                    *(float2*)(Cf + (size_t)row * N + c) = o;
                } else {
                    __nv_bfloat162 h, l;
                    h.x = __float2bfloat16(v0);
                    h.y = __float2bfloat16(v1);
                    l.x = __float2bfloat16(v0 - __bfloat162float(h.x));
                    l.y = __float2bfloat16(v1 - __bfloat162float(h.y));
                    *(__nv_bfloat162*)(Chi + (size_t)row * N + c) = h;
                    *(__nv_bfloat162*)(Clo + (size_t)row * N + c) = l;
                }
            }
        }
    }
}

// ===================== attention small ops =====================
__global__ void __launch_bounds__(256) gram_kernel(
    const float* __restrict__ q, const float* __restrict__ k,
    float* __restrict__ Gpart)
{
    const int bh = blockIdx.x;
    const int ns = blockIdx.y;
    const int b = bh >> 4, h = bh & 15;
    const int tid = threadIdx.x;
    __shared__ float Qs[32][68];
    __shared__ float Ks[32][68];

    float acc[4][4];
#pragma unroll
    for (int i = 0; i < 4; i++)
#pragma unroll
        for (int j = 0; j < 4; j++) acc[i][j] = 0.0f;

    const int ty = tid >> 4, tx = tid & 15;
    const size_t base = ((size_t)b * NN) * DD + h * DH;
    const int n0s = ns * 512;

    for (int n0 = n0s; n0 < n0s + 512; n0 += 32) {
#pragma unroll
        for (int r = 0; r < 2; r++) {
            int idx4 = tid + r * 256;
            int nn = idx4 >> 4;
            int i4 = (idx4 & 15) * 4;
            float4 qv = *(const float4*)(q + base + (size_t)(n0 + nn) * DD + i4);
            float4 kv = *(const float4*)(k + base + (size_t)(n0 + nn) * DD + i4);
            *(float4*)&Qs[nn][i4] = qv;
            *(float4*)&Ks[nn][i4] = kv;
        }
        __syncthreads();
#pragma unroll
        for (int kk = 0; kk < 32; kk++) {
            float qr[4], kr[4];
#pragma unroll
            for (int i = 0; i < 4; i++) qr[i] = Qs[kk][ty * 4 + i];
#pragma unroll
            for (int j = 0; j < 4; j++) kr[j] = Ks[kk][tx * 4 + j];
#pragma unroll
            for (int i = 0; i < 4; i++)
#pragma unroll
                for (int j = 0; j < 4; j++) acc[i][j] += qr[i] * kr[j];
        }
        __syncthreads();
    }

    float* Gout = Gpart + ((size_t)bh * 8 + ns) * (DH * DH);
#pragma unroll
    for (int i = 0; i < 4; i++)
#pragma unroll
        for (int j = 0; j < 4; j++)
            Gout[(ty * 4 + i) * DH + tx * 4 + j] = acc[i][j];
}

__global__ void __launch_bounds__(256) weights_kernel(
    const float* __restrict__ Gpart, float* __restrict__ Wt)
{
    const int bh = blockIdx.x;
    const int tid = threadIdx.x;
    __shared__ float Gs[DH][DH];
    __shared__ float ct[DH], st[DH];

    for (int e = tid; e < DH * DH; e += 256) {
        float s = 0.0f;
#pragma unroll
        for (int p = 0; p < 8; p++)
            s += Gpart[((size_t)bh * 8 + p) * (DH * DH) + e];
        Gs[e >> 6][e & 63] = s;
    }
    if (tid < DH) {
        float a = 6.283185307179586f * (float)tid / 64.0f;
        ct[tid] = cosf(a);
        st[tid] = sinf(a);
    }
    __syncthreads();

    const int i = tid >> 2;
    const int j0 = (tid & 3) * 16;
    for (int jj = 0; jj < 16; jj++) {
        const int j = j0 + jj;
        float re = 0.0f, im = 0.0f;
#pragma unroll
        for (int kk = 0; kk < DH; kk++) {
            const int t = (kk * j) & 63;
            const float g = Gs[i][kk];
            re += g * ct[t];
            im += g * st[t];
        }
        Wt[(size_t)bh * (DH * DH) + i * DH + j] = sqrtf(re * re + im * im);
    }
}

// attnpre (weighted V) emitted directly as bf16 hi/lo pairs for the O-projection GEMM
__global__ void __launch_bounds__(256) applyw_kernel(
    const float* __restrict__ v, const float* __restrict__ Wt,
    __nv_bfloat16* __restrict__ ohi, __nv_bfloat16* __restrict__ olo)
{
    const int bh = blockIdx.x;
    const int b = bh >> 4, h = bh & 15;
    const int tid = threadIdx.x;
    __shared__ float Ws[DH][DH + 1];
    __shared__ float Vs[4][DH];

    for (int e = tid; e < DH * DH; e += 256)
        Ws[e >> 6][e & 63] = Wt[(size_t)bh * (DH * DH) + e];
    __syncthreads();

    const int nn = tid >> 6;
    const int i = tid & 63;
    const size_t base = ((size_t)b * NN) * DD + h * DH;
    const int n0 = blockIdx.y * 64;

    for (int n = n0; n < n0 + 64; n += 4) {
        Vs[nn][i] = v[base + (size_t)(n + nn) * DD + i];
        __syncthreads();
        float acc = 0.0f;
#pragma unroll
        for (int j = 0; j < DH; j++) acc += Ws[i][j] * Vs[nn][j];
        const size_t idx = base + (size_t)(n + nn) * DD + i;
        const __nv_bfloat16 hv = __float2bfloat16(acc);
        ohi[idx] = hv;
        olo[idx] = __float2bfloat16(acc - __bfloat162float(hv));
        __syncthreads();
    }
}

// ===================== global-std reduction + norm =====================
__global__ void __launch_bounds__(256) red1_kernel(const float* __restrict__ x, size_t n)
{
    float s = 0.0f, s2 = 0.0f;
    const size_t stride = (size_t)gridDim.x * blockDim.x;
    for (size_t idx = (size_t)blockIdx.x * blockDim.x + threadIdx.x; idx < n; idx += stride) {
        const float vv = x[idx];
        s += vv;
        s2 += vv * vv;
    }
#pragma unroll
    for (int o = 16; o > 0; o >>= 1) {
        s += __shfl_down_sync(0xFFFFFFFFu, s, o);
        s2 += __shfl_down_sync(0xFFFFFFFFu, s2, o);
    }
    __shared__ double sh[2][8];
    const int w = threadIdx.x >> 5, l = threadIdx.x & 31;
    if (l == 0) { sh[0][w] = (double)s; sh[1][w] = (double)s2; }
    __syncthreads();
    if (threadIdx.x == 0) {
        double a = 0.0, b = 0.0;
#pragma unroll
        for (int i = 0; i < 8; i++) { a += sh[0][i]; b += sh[1][i]; }
        g_part[blockIdx.x][0] = a;
        g_part[blockIdx.x][1] = b;
    }
}

__global__ void __launch_bounds__(256) red2_kernel(int nb)
{
    double a = 0.0, b = 0.0;
    for (int i = threadIdx.x; i < nb; i += 256) { a += g_part[i][0]; b += g_part[i][1]; }
    __shared__ double sa[256], sb[256];
    sa[threadIdx.x] = a;
    sb[threadIdx.x] = b;
    __syncthreads();
    for (int o = 128; o > 0; o >>= 1) {
        if (threadIdx.x < o) { sa[threadIdx.x] += sa[threadIdx.x + o]; sb[threadIdx.x] += sb[threadIdx.x + o]; }
        __syncthreads();
    }
    if (threadIdx.x == 0) { g_red[0] = sa[0]; g_red[1] = sb[0]; }
}

template <bool SPLIT>
__global__ void __launch_bounds__(256) norm_kernel(
    const float* __restrict__ x, const float* __restrict__ alpha,
    const float* __restrict__ beta, const float* __restrict__ eps,
    float* __restrict__ y, __nv_bfloat16* __restrict__ yhi,
    __nv_bfloat16* __restrict__ ylo, size_t n)
{
    const double Md = (double)n;
    const double mean = g_red[0] / Md;
    const double var = (g_red[1] - Md * mean * mean) / (Md - 1.0);
    const float sd = (float)sqrt(var);

    const size_t n4 = n >> 2;
    const size_t stride = (size_t)gridDim.x * blockDim.x;
    for (size_t i4 = (size_t)blockIdx.x * blockDim.x + threadIdx.x; i4 < n4; i4 += stride) {
        float4 v = ((const float4*)x)[i4];
        const int d = (int)((i4 * 4) & (DD - 1));
        v.x = v.x / (sd + eps[d + 0]) * alpha[d + 0] + beta[d + 0];
        v.y = v.y / (sd + eps[d + 1]) * alpha[d + 1] + beta[d + 1];
        v.z = v.z / (sd + eps[d + 2]) * alpha[d + 2] + beta[d + 2];
        v.w = v.w / (sd + eps[d + 3]) * alpha[d + 3] + beta[d + 3];
        ((float4*)y)[i4] = v;
        if (SPLIT) {
            __nv_bfloat16 h0 = __float2bfloat16(v.x);
            __nv_bfloat16 h1 = __float2bfloat16(v.y);
            __nv_bfloat16 h2 = __float2bfloat16(v.z);
            __nv_bfloat16 h3 = __float2bfloat16(v.w);
            __nv_bfloat162 hA; hA.x = h0; hA.y = h1;
            __nv_bfloat162 hB; hB.x = h2; hB.y = h3;
            __nv_bfloat162 lA; lA.x = __float2bfloat16(v.x - __bfloat162float(h0));
                               lA.y = __float2bfloat16(v.y - __bfloat162float(h1));
            __nv_bfloat162 lB; lB.x = __float2bfloat16(v.z - __bfloat162float(h2));
                               lB.y = __float2bfloat16(v.w - __bfloat162float(h3));
            ((__nv_bfloat162*)yhi)[i4 * 2 + 0] = hA;
            ((__nv_bfloat162*)yhi)[i4 * 2 + 1] = hB;
            ((__nv_bfloat162*)ylo)[i4 * 2 + 0] = lA;
            ((__nv_bfloat162*)ylo)[i4 * 2 + 1] = lB;
        }
    }
}

// ===================== launch =====================
extern "C" void kernel_launch(void* const* d_in, const int* in_sizes, int n_in,
                              void* d_out, int out_size)
{
    const float* x    = (const float*)d_in[0];
    const float* wq_w = (const float*)d_in[1];
    const float* wq_b = (const float*)d_in[2];
    const float* wk_w = (const float*)d_in[3];
    const float* wk_b = (const float*)d_in[4];
    const float* wv_w = (const float*)d_in[5];
    const float* wv_b = (const float*)d_in[6];
    const float* wo_w = (const float*)d_in[7];
    const float* wo_b = (const float*)d_in[8];
    const float* w1   = (const float*)d_in[9];
    const float* b1   = (const float*)d_in[10];
    const float* w2   = (const float*)d_in[11];
    const float* b2   = (const float*)d_in[12];
    const float* an_a = (const float*)d_in[13];
    const float* an_b = (const float*)d_in[14];
    const float* an_e = (const float*)d_in[15];
    const float* mn_a = (const float*)d_in[16];
    const float* mn_b = (const float*)d_in[17];
    const float* mn_e = (const float*)d_in[18];
    float* out = (float*)d_out;

    float *q, *k, *v, *attn, *out1, *Gpart, *Wt;
    cudaGetSymbolAddress((void**)&q, g_q);
    cudaGetSymbolAddress((void**)&k, g_k);
    cudaGetSymbolAddress((void**)&v, g_v);
    cudaGetSymbolAddress((void**)&attn, g_attn);
    cudaGetSymbolAddress((void**)&out1, g_out1);
    cudaGetSymbolAddress((void**)&Gpart, g_Gpart);
    cudaGetSymbolAddress((void**)&Wt, g_Wt);

    __nv_bfloat16 *xhi, *xlo, *aphi, *aplo, *athi, *atlo, *hhi, *hlo;
    __nv_bfloat16 *wqh, *wql, *wkh, *wkl, *wvh, *wvl, *woh, *wol, *w1h, *w1l, *w2h, *w2l;
    cudaGetSymbolAddress((void**)&xhi, g_xhi);   cudaGetSymbolAddress((void**)&xlo, g_xlo);
    cudaGetSymbolAddress((void**)&aphi, g_aphi); cudaGetSymbolAddress((void**)&aplo, g_aplo);
    cudaGetSymbolAddress((void**)&athi, g_athi); cudaGetSymbolAddress((void**)&atlo, g_atlo);
    cudaGetSymbolAddress((void**)&hhi, g_hhi);   cudaGetSymbolAddress((void**)&hlo, g_hlo);
    cudaGetSymbolAddress((void**)&wqh, g_wqhi);  cudaGetSymbolAddress((void**)&wql, g_wqlo);
    cudaGetSymbolAddress((void**)&wkh, g_wkhi);  cudaGetSymbolAddress((void**)&wkl, g_wklo);
    cudaGetSymbolAddress((void**)&wvh, g_wvhi);  cudaGetSymbolAddress((void**)&wvl, g_wvlo);
    cudaGetSymbolAddress((void**)&woh, g_wohi);  cudaGetSymbolAddress((void**)&wol, g_wolo);
    cudaGetSymbolAddress((void**)&w1h, g_w1hi);  cudaGetSymbolAddress((void**)&w1l, g_w1lo);
    cudaGetSymbolAddress((void**)&w2h, g_w2hi);  cudaGetSymbolAddress((void**)&w2l, g_w2lo);

    cudaFuncSetAttribute(gemm_mma<false, false, 0>, cudaFuncAttributeMaxDynamicSharedMemorySize, GW_SMEM);
    cudaFuncSetAttribute(gemm_mma<true,  false, 0>, cudaFuncAttributeMaxDynamicSharedMemorySize, GW_SMEM);
    cudaFuncSetAttribute(gemm_mma<false, true,  1>, cudaFuncAttributeMaxDynamicSharedMemorySize, GW_SMEM);

    // ---- convert inputs to bf16 hi/lo ----
    split_kernel<<<1024, 256>>>(x, xhi, xlo, TOT / 4);
    split_kernel<<<256, 256>>>(wq_w, wqh, wql, (size_t)DD * DD / 4);
    split_kernel<<<256, 256>>>(wk_w, wkh, wkl, (size_t)DD * DD / 4);
    split_kernel<<<256, 256>>>(wv_w, wvh, wvl, (size_t)DD * DD / 4);
    split_kernel<<<256, 256>>>(wo_w, woh, wol, (size_t)DD * DD / 4);
    split_kernel<<<512, 256>>>(w1, w1h, w1l, (size_t)FF * DD / 4);
    split_kernel<<<512, 256>>>(w2, w2h, w2l, (size_t)DD * FF / 4);

    const dim3 gProj(DD / GW_BN, MM / GW_BM);   // (8, 128)
    const dim3 gMlp1(FF / GW_BN, MM / GW_BM);   // (32, 128)

    // ---- Q/K/V projections ----
    gemm_mma<false, false, 0><<<gProj, 256, GW_SMEM>>>(xhi, xlo, wqh, wql, wq_b, nullptr, q, nullptr, nullptr, MM, DD, DD);
    gemm_mma<false, false, 0><<<gProj, 256, GW_SMEM>>>(xhi, xlo, wkh, wkl, wk_b, nullptr, k, nullptr, nullptr, MM, DD, DD);
    gemm_mma<false, false, 0><<<gProj, 256, GW_SMEM>>>(xhi, xlo, wvh, wvl, wv_b, nullptr, v, nullptr, nullptr, MM, DD, DD);

    // ---- FFT attention (collapsed form) ----
    gram_kernel<<<dim3(BB * HH, 8), 256>>>(q, k, Gpart);
    weights_kernel<<<BB * HH, 256>>>(Gpart, Wt);
    applyw_kernel<<<dim3(BB * HH, NN / 64), 256>>>(v, Wt, aphi, aplo);

    // ---- output projection + residual ----
    gemm_mma<true, false, 0><<<gProj, 256, GW_SMEM>>>(aphi, aplo, woh, wol, wo_b, x, attn, nullptr, nullptr, MM, DD, DD);

    // ---- rmsnorm 1 (global std), also emits bf16 hi/lo for MLP1 ----
    red1_kernel<<<2048, 256>>>(attn, TOT);
    red2_kernel<<<1, 256>>>(2048);
    norm_kernel<true><<<2048, 256>>>(attn, an_a, an_b, an_e, attn, athi, atlo, TOT);

    // ---- MLP ----
    gemm_mma<false, true, 1><<<gMlp1, 256, GW_SMEM>>>(athi, atlo, w1h, w1l, b1, nullptr, nullptr, hhi, hlo, MM, FF, DD);
    gemm_mma<true, false, 0><<<gProj, 256, GW_SMEM>>>(hhi, hlo, w2h, w2l, b2, attn, out1, nullptr, nullptr, MM, DD, FF);

    // ---- rmsnorm 2 -> final output ----
    red1_kernel<<<2048, 256>>>(out1, TOT);
    red2_kernel<<<1, 256>>>(2048);
    norm_kernel<false><<<2048, 256>>>(out1, mn_a, mn_b, mn_e, out, nullptr, nullptr, TOT);
}

// round 5
// speedup vs baseline: 4.4148x; 1.5658x over previous
#include <cuda_runtime.h>
#include <cuda_bf16.h>
#include <cuda_fp16.h>
#include <cstdint>
#include <math.h>

// Problem dims (fixed by the dataset)
#define BB 4
#define NN 4096
#define DD 1024
#define HH 16
#define DH 64
#define FF 4096
#define MM (BB * NN)          // 16384
#define TOT ((size_t)MM * DD) // 16,777,216

// ===================== helpers =====================
__device__ __forceinline__ uint32_t smem_u32(const void* p) {
    uint32_t a;
    asm("{ .reg .u64 t; cvta.to.shared.u64 t, %1; cvt.u32.u64 %0, t; }" : "=r"(a) : "l"(p));
    return a;
}
__device__ __forceinline__ void cp_async16(uint32_t dst, const void* src) {
    asm volatile("cp.async.cg.shared.global [%0], [%1], 16;"
                 :: "r"(dst), "l"(__cvta_generic_to_global(src)));
}
__device__ __forceinline__ void cp_commit() { asm volatile("cp.async.commit_group;" ::: "memory"); }
__device__ __forceinline__ void cp_wait0()  { asm volatile("cp.async.wait_group 0;" ::: "memory"); }
__device__ __forceinline__ void cp_wait1()  { asm volatile("cp.async.wait_group 1;" ::: "memory"); }

#define MMA16816(d, a, b0, b1) \
    asm volatile("mma.sync.aligned.m16n8k16.row.col.f32.bf16.bf16.f32 " \
        "{%0,%1,%2,%3}, {%4,%5,%6,%7}, {%8,%9}, {%0,%1,%2,%3};" \
        : "+f"((d)[0]), "+f"((d)[1]), "+f"((d)[2]), "+f"((d)[3]) \
        : "r"((a)[0]), "r"((a)[1]), "r"((a)[2]), "r"((a)[3]), "r"(b0), "r"(b1))

#define MMAF16(d, a, b0, b1) \
    asm volatile("mma.sync.aligned.m16n8k16.row.col.f32.f16.f16.f32 " \
        "{%0,%1,%2,%3}, {%4,%5,%6,%7}, {%8,%9}, {%0,%1,%2,%3};" \
        : "+f"((d)[0]), "+f"((d)[1]), "+f"((d)[2]), "+f"((d)[3]) \
        : "r"((a)[0]), "r"((a)[1]), "r"((a)[2]), "r"((a)[3]), "r"(b0), "r"(b1))

#define LDMX4(r, addr) \
    asm volatile("ldmatrix.sync.aligned.m8n8.x4.shared.b16 {%0,%1,%2,%3}, [%4];" \
        : "=r"((r)[0]), "=r"((r)[1]), "=r"((r)[2]), "=r"((r)[3]) : "r"(addr))

// ===================== scratch (static device globals) =====================
__device__ float g_q[MM * DD];
__device__ float g_k[MM * DD];
__device__ float g_v[MM * DD];
__device__ float g_attn[MM * DD];
__device__ float g_out1[MM * DD];
__device__ float g_Gpart[BB * HH * 8 * DH * DH];
__device__ float g_Wt[BB * HH * DH * DH];
__device__ double g_part[4096][2];
__device__ double g_red[2];

__device__ __nv_bfloat16 g_xhi[MM * DD],  g_xlo[MM * DD];
__device__ __nv_bfloat16 g_aphi[MM * DD], g_aplo[MM * DD];
__device__ __nv_bfloat16 g_wqhi[DD * DD], g_wqlo[DD * DD];
__device__ __nv_bfloat16 g_wkhi[DD * DD], g_wklo[DD * DD];
__device__ __nv_bfloat16 g_wvhi[DD * DD], g_wvlo[DD * DD];
__device__ __nv_bfloat16 g_wohi[DD * DD], g_wolo[DD * DD];

// fp16 MLP path
__device__ __half g_w1f[FF * DD];
__device__ __half g_w2f[DD * FF];
__device__ __half g_atf[MM * DD];
__device__ __half g_hf[(size_t)MM * FF];

// ===================== fp32 -> bf16 hi/lo split =====================
__global__ void __launch_bounds__(256) split_kernel(
    const float* __restrict__ src, __nv_bfloat16* __restrict__ hi,
    __nv_bfloat16* __restrict__ lo, size_t n4)
{
    const size_t stride = (size_t)gridDim.x * blockDim.x;
    for (size_t i4 = (size_t)blockIdx.x * blockDim.x + threadIdx.x; i4 < n4; i4 += stride) {
        float4 v = ((const float4*)src)[i4];
        __nv_bfloat16 h0 = __float2bfloat16(v.x);
        __nv_bfloat16 h1 = __float2bfloat16(v.y);
        __nv_bfloat16 h2 = __float2bfloat16(v.z);
        __nv_bfloat16 h3 = __float2bfloat16(v.w);
        __nv_bfloat162 hA; hA.x = h0; hA.y = h1;
        __nv_bfloat162 hB; hB.x = h2; hB.y = h3;
        __nv_bfloat162 lA; lA.x = __float2bfloat16(v.x - __bfloat162float(h0));
                           lA.y = __float2bfloat16(v.y - __bfloat162float(h1));
        __nv_bfloat162 lB; lB.x = __float2bfloat16(v.z - __bfloat162float(h2));
                           lB.y = __float2bfloat16(v.w - __bfloat162float(h3));
        ((__nv_bfloat162*)hi)[i4 * 2 + 0] = hA;
        ((__nv_bfloat162*)hi)[i4 * 2 + 1] = hB;
        ((__nv_bfloat162*)lo)[i4 * 2 + 0] = lA;
        ((__nv_bfloat162*)lo)[i4 * 2 + 1] = lB;
    }
}

// ===================== fp32 -> fp16 convert =====================
__global__ void __launch_bounds__(256) cvtf16_kernel(
    const float* __restrict__ src, __half* __restrict__ dst, size_t n4)
{
    const size_t stride = (size_t)gridDim.x * blockDim.x;
    for (size_t i4 = (size_t)blockIdx.x * blockDim.x + threadIdx.x; i4 < n4; i4 += stride) {
        float4 v = ((const float4*)src)[i4];
        ((__half2*)dst)[i4 * 2 + 0] = __floats2half2_rn(v.x, v.y);
        ((__half2*)dst)[i4 * 2 + 1] = __floats2half2_rn(v.z, v.w);
    }
}

// ===================== bf16 hi/lo HMMA GEMM (3 products) =====================
#define GW_BM 128
#define GW_BN 128
#define GW_BK 32
#define ROWB 80                    // padded row pitch (bytes): conflict-free ldmatrix
#define BUFB (128 * ROWB)          // 10240 per buffer
#define STAGEB (4 * BUFB)          // Ahi/Alo/Bhi/Blo
#define GW_SMEM (2 * STAGEB)       // 81920

template <bool HAS_RES, bool GELU, int OUTMODE> // 0: fp32 out; 1: bf16 hi/lo out
__global__ void __launch_bounds__(256, 2) gemm_mma(
    const __nv_bfloat16* __restrict__ Ahi, const __nv_bfloat16* __restrict__ Alo,
    const __nv_bfloat16* __restrict__ Bhi, const __nv_bfloat16* __restrict__ Blo,
    const float* __restrict__ bias, const float* __restrict__ res,
    float* __restrict__ Cf, __nv_bfloat16* __restrict__ Chi, __nv_bfloat16* __restrict__ Clo,
    int M, int N, int K)
{
    extern __shared__ char sm[];
    const int tid = threadIdx.x;
    const int wid = tid >> 5;
    const int lane = tid & 31;
    const int wm = wid & 3;
    const int wn = wid >> 2;
    const int bm = blockIdx.y * GW_BM;
    const int bn = blockIdx.x * GW_BN;
    const int KT = K / GW_BK;
    const uint32_t smb = smem_u32(sm);

    auto load_stage = [&](int kt, uint32_t sb) {
        const int k0 = kt * GW_BK;
#pragma unroll
        for (int i = 0; i < 8; i++) {
            const int c = tid + i * 256;
            const int buf = c >> 9;
            const int cc = c & 511;
            const int row = cc >> 2;
            const int qq = cc & 3;
            const __nv_bfloat16* gb = (buf == 0) ? Ahi : (buf == 1) ? Alo
                                     : (buf == 2) ? Bhi : Blo;
            const int grow = ((buf < 2) ? bm : bn) + row;
            const void* src = gb + (size_t)grow * K + k0 + qq * 8;
            cp_async16(sb + buf * BUFB + row * ROWB + qq * 16, src);
        }
    };

    float acc[2][8][4];
#pragma unroll
    for (int mt = 0; mt < 2; mt++)
#pragma unroll
        for (int nt = 0; nt < 8; nt++)
#pragma unroll
            for (int r = 0; r < 4; r++) acc[mt][nt][r] = 0.0f;

    load_stage(0, smb);
    cp_commit();

    const int lr = lane & 7;
    const int a_row = wm * 32 + lr + ((lane & 8) ? 8 : 0);
    const int a_kb  = (lane & 16) ? 16 : 0;
    const int b_row = wn * 64 + lr + ((lane & 16) ? 8 : 0);
    const int b_kb  = (lane & 8) ? 16 : 0;

    for (int kt = 0; kt < KT; kt++) {
        const uint32_t sb = smb + (uint32_t)(kt & 1) * STAGEB;
        if (kt + 1 < KT) {
            load_stage(kt + 1, smb + (uint32_t)((kt + 1) & 1) * STAGEB);
            cp_commit();
            cp_wait1();
        } else {
            cp_wait0();
        }
        __syncthreads();

        const uint32_t As = sb;
        const uint32_t Bs = sb + 2 * BUFB;

#pragma unroll
        for (int k16 = 0; k16 < 2; k16++) {
            const int kc = k16 * 32;
            uint32_t ah[2][4], al[2][4];
#pragma unroll
            for (int mt = 0; mt < 2; mt++) {
                const uint32_t aAddr = As + (uint32_t)((a_row + mt * 16) * ROWB + kc + a_kb);
                LDMX4(ah[mt], aAddr);
                LDMX4(al[mt], aAddr + BUFB);
            }
#pragma unroll
            for (int p = 0; p < 4; p++) {
                uint32_t bh[4], bl[4];
                const uint32_t bAddr = Bs + (uint32_t)((b_row + p * 16) * ROWB + kc + b_kb);
                LDMX4(bh, bAddr);
                LDMX4(bl, bAddr + BUFB);
#pragma unroll
                for (int sub = 0; sub < 2; sub++) {
                    const int nt = p * 2 + sub;
                    const uint32_t b0h = bh[sub * 2], b1h = bh[sub * 2 + 1];
                    const uint32_t b0l = bl[sub * 2], b1l = bl[sub * 2 + 1];
#pragma unroll
                    for (int mt = 0; mt < 2; mt++) {
                        MMA16816(acc[mt][nt], ah[mt], b0h, b1h);
                        MMA16816(acc[mt][nt], ah[mt], b0l, b1l);
                        MMA16816(acc[mt][nt], al[mt], b0h, b1h);
                    }
                }
            }
        }
        __syncthreads();
    }

#pragma unroll
    for (int mt = 0; mt < 2; mt++) {
        const int r0 = bm + wm * 32 + mt * 16 + (lane >> 2);
#pragma unroll
        for (int nt = 0; nt < 8; nt++) {
            const int c = bn + wn * 64 + nt * 8 + ((lane & 3) << 1);
            const float b0 = bias[c], b1 = bias[c + 1];
#pragma unroll
            for (int half = 0; half < 2; half++) {
                const int row = r0 + half * 8;
                float v0 = acc[mt][nt][half * 2 + 0] + b0;
                float v1 = acc[mt][nt][half * 2 + 1] + b1;
                if (HAS_RES) {
                    const float2 rr = *(const float2*)(res + (size_t)row * N + c);
                    v0 += rr.x; v1 += rr.y;
                }
                if (GELU) {
                    v0 = 0.5f * v0 * (1.0f + erff(v0 * 0.70710678118654752f));
                    v1 = 0.5f * v1 * (1.0f + erff(v1 * 0.70710678118654752f));
                }
                if (OUTMODE == 0) {
                    float2 o; o.x = v0; o.y = v1;
                    *(float2*)(Cf + (size_t)row * N + c) = o;
                } else {
                    __nv_bfloat162 h, l;
                    h.x = __float2bfloat16(v0);
                    h.y = __float2bfloat16(v1);
                    l.x = __float2bfloat16(v0 - __bfloat162float(h.x));
                    l.y = __float2bfloat16(v1 - __bfloat162float(h.y));
                    *(__nv_bfloat162*)(Chi + (size_t)row * N + c) = h;
                    *(__nv_bfloat162*)(Clo + (size_t)row * N + c) = l;
                }
            }
        }
    }
}

// ===================== fp16 single-product HMMA GEMM (MLP path) =====================
#define F16_STAGEB (2 * BUFB)      // A @0, B @BUFB
#define F16_SMEM (2 * F16_STAGEB)  // 40960

template <bool HAS_RES, bool GELU, bool OUTF16>
__global__ void __launch_bounds__(256, 2) gemm_f16(
    const __half* __restrict__ A, const __half* __restrict__ B,
    const float* __restrict__ bias, const float* __restrict__ res,
    float* __restrict__ Cf, __half* __restrict__ Ch,
    int M, int N, int K)
{
    extern __shared__ char sm[];
    const int tid = threadIdx.x;
    const int wid = tid >> 5;
    const int lane = tid & 31;
    const int wm = wid & 3;
    const int wn = wid >> 2;
    const int bm = blockIdx.y * GW_BM;
    const int bn = blockIdx.x * GW_BN;
    const int KT = K / GW_BK;
    const uint32_t smb = smem_u32(sm);

    auto load_stage = [&](int kt, uint32_t sb) {
        const int k0 = kt * GW_BK;
#pragma unroll
        for (int i = 0; i < 4; i++) {
            const int c = tid + i * 256;      // 0..1023
            const int buf = c >> 9;           // 0:A 1:B
            const int cc = c & 511;
            const int row = cc >> 2;
            const int qq = cc & 3;
            const __half* gb = buf ? B : A;
            const int grow = (buf ? bn : bm) + row;
            const void* src = gb + (size_t)grow * K + k0 + qq * 8;
            cp_async16(sb + buf * BUFB + row * ROWB + qq * 16, src);
        }
    };

    float acc[2][8][4];
#pragma unroll
    for (int mt = 0; mt < 2; mt++)
#pragma unroll
        for (int nt = 0; nt < 8; nt++)
#pragma unroll
            for (int r = 0; r < 4; r++) acc[mt][nt][r] = 0.0f;

    load_stage(0, smb);
    cp_commit();

    const int lr = lane & 7;
    const int a_row = wm * 32 + lr + ((lane & 8) ? 8 : 0);
    const int a_kb  = (lane & 16) ? 16 : 0;
    const int b_row = wn * 64 + lr + ((lane & 16) ? 8 : 0);
    const int b_kb  = (lane & 8) ? 16 : 0;

    for (int kt = 0; kt < KT; kt++) {
        const uint32_t sb = smb + (uint32_t)(kt & 1) * F16_STAGEB;
        if (kt + 1 < KT) {
            load_stage(kt + 1, smb + (uint32_t)((kt + 1) & 1) * F16_STAGEB);
            cp_commit();
            cp_wait1();
        } else {
            cp_wait0();
        }
        __syncthreads();

        const uint32_t As = sb;
        const uint32_t Bs = sb + BUFB;

#pragma unroll
        for (int k16 = 0; k16 < 2; k16++) {
            const int kc = k16 * 32;
            uint32_t af[2][4];
#pragma unroll
            for (int mt = 0; mt < 2; mt++)
                LDMX4(af[mt], As + (uint32_t)((a_row + mt * 16) * ROWB + kc + a_kb));
#pragma unroll
            for (int p = 0; p < 4; p++) {
                uint32_t bf[4];
                LDMX4(bf, Bs + (uint32_t)((b_row + p * 16) * ROWB + kc + b_kb));
#pragma unroll
                for (int sub = 0; sub < 2; sub++) {
                    const int nt = p * 2 + sub;
#pragma unroll
                    for (int mt = 0; mt < 2; mt++)
                        MMAF16(acc[mt][nt], af[mt], bf[sub * 2], bf[sub * 2 + 1]);
                }
            }
        }
        __syncthreads();
    }

#pragma unroll
    for (int mt = 0; mt < 2; mt++) {
        const int r0 = bm + wm * 32 + mt * 16 + (lane >> 2);
#pragma unroll
        for (int nt = 0; nt < 8; nt++) {
            const int c = bn + wn * 64 + nt * 8 + ((lane & 3) << 1);
            const float b0 = bias[c], b1 = bias[c + 1];
#pragma unroll
            for (int half = 0; half < 2; half++) {
                const int row = r0 + half * 8;
                float v0 = acc[mt][nt][half * 2 + 0] + b0;
                float v1 = acc[mt][nt][half * 2 + 1] + b1;
                if (HAS_RES) {
                    const float2 rr = *(const float2*)(res + (size_t)row * N + c);
                    v0 += rr.x; v1 += rr.y;
                }
                if (GELU) {
                    v0 = 0.5f * v0 * (1.0f + erff(v0 * 0.70710678118654752f));
                    v1 = 0.5f * v1 * (1.0f + erff(v1 * 0.70710678118654752f));
                }
                if (OUTF16) {
                    *(__half2*)(Ch + (size_t)row * N + c) = __floats2half2_rn(v0, v1);
                } else {
                    float2 o; o.x = v0; o.y = v1;
                    *(float2*)(Cf + (size_t)row * N + c) = o;
                }
            }
        }
    }
}

// ===================== attention small ops =====================
__global__ void __launch_bounds__(256) gram_kernel(
    const float* __restrict__ q, const float* __restrict__ k,
    float* __restrict__ Gpart)
{
    const int bh = blockIdx.x;
    const int ns = blockIdx.y;
    const int b = bh >> 4, h = bh & 15;
    const int tid = threadIdx.x;
    __shared__ float Qs[32][68];
    __shared__ float Ks[32][68];

    float acc[4][4];
#pragma unroll
    for (int i = 0; i < 4; i++)
#pragma unroll
        for (int j = 0; j < 4; j++) acc[i][j] = 0.0f;

    const int ty = tid >> 4, tx = tid & 15;
    const size_t base = ((size_t)b * NN) * DD + h * DH;
    const int n0s = ns * 512;

    for (int n0 = n0s; n0 < n0s + 512; n0 += 32) {
#pragma unroll
        for (int r = 0; r < 2; r++) {
            int idx4 = tid + r * 256;
            int nn = idx4 >> 4;
            int i4 = (idx4 & 15) * 4;
            float4 qv = *(const float4*)(q + base + (size_t)(n0 + nn) * DD + i4);
            float4 kv = *(const float4*)(k + base + (size_t)(n0 + nn) * DD + i4);
            *(float4*)&Qs[nn][i4] = qv;
            *(float4*)&Ks[nn][i4] = kv;
        }
        __syncthreads();
#pragma unroll
        for (int kk = 0; kk < 32; kk++) {
            float qr[4], kr[4];
#pragma unroll
            for (int i = 0; i < 4; i++) qr[i] = Qs[kk][ty * 4 + i];
#pragma unroll
            for (int j = 0; j < 4; j++) kr[j] = Ks[kk][tx * 4 + j];
#pragma unroll
            for (int i = 0; i < 4; i++)
#pragma unroll
                for (int j = 0; j < 4; j++) acc[i][j] += qr[i] * kr[j];
        }
        __syncthreads();
    }

    float* Gout = Gpart + ((size_t)bh * 8 + ns) * (DH * DH);
#pragma unroll
    for (int i = 0; i < 4; i++)
#pragma unroll
        for (int j = 0; j < 4; j++)
            Gout[(ty * 4 + i) * DH + tx * 4 + j] = acc[i][j];
}

__global__ void __launch_bounds__(256) weights_kernel(
    const float* __restrict__ Gpart, float* __restrict__ Wt)
{
    const int bh = blockIdx.x;
    const int tid = threadIdx.x;
    __shared__ float Gs[DH][DH];
    __shared__ float ct[DH], st[DH];

    for (int e = tid; e < DH * DH; e += 256) {
        float s = 0.0f;
#pragma unroll
        for (int p = 0; p < 8; p++)
            s += Gpart[((size_t)bh * 8 + p) * (DH * DH) + e];
        Gs[e >> 6][e & 63] = s;
    }
    if (tid < DH) {
        float a = 6.283185307179586f * (float)tid / 64.0f;
        ct[tid] = cosf(a);
        st[tid] = sinf(a);
    }
    __syncthreads();

    const int i = tid >> 2;
    const int j0 = (tid & 3) * 16;
    for (int jj = 0; jj < 16; jj++) {
        const int j = j0 + jj;
        float re = 0.0f, im = 0.0f;
#pragma unroll
        for (int kk = 0; kk < DH; kk++) {
            const int t = (kk * j) & 63;
            const float g = Gs[i][kk];
            re += g * ct[t];
            im += g * st[t];
        }
        Wt[(size_t)bh * (DH * DH) + i * DH + j] = sqrtf(re * re + im * im);
    }
}

__global__ void __launch_bounds__(256) applyw_kernel(
    const float* __restrict__ v, const float* __restrict__ Wt,
    __nv_bfloat16* __restrict__ ohi, __nv_bfloat16* __restrict__ olo)
{
    const int bh = blockIdx.x;
    const int b = bh >> 4, h = bh & 15;
    const int tid = threadIdx.x;
    __shared__ float Ws[DH][DH + 1];
    __shared__ float Vs[4][DH];

    for (int e = tid; e < DH * DH; e += 256)
        Ws[e >> 6][e & 63] = Wt[(size_t)bh * (DH * DH) + e];
    __syncthreads();

    const int nn = tid >> 6;
    const int i = tid & 63;
    const size_t base = ((size_t)b * NN) * DD + h * DH;
    const int n0 = blockIdx.y * 64;

    for (int n = n0; n < n0 + 64; n += 4) {
        Vs[nn][i] = v[base + (size_t)(n + nn) * DD + i];
        __syncthreads();
        float acc = 0.0f;
#pragma unroll
        for (int j = 0; j < DH; j++) acc += Ws[i][j] * Vs[nn][j];
        const size_t idx = base + (size_t)(n + nn) * DD + i;
        const __nv_bfloat16 hv = __float2bfloat16(acc);
        ohi[idx] = hv;
        olo[idx] = __float2bfloat16(acc - __bfloat162float(hv));
        __syncthreads();
    }
}

// ===================== global-std reduction + norm =====================
__global__ void __launch_bounds__(256) red1_kernel(const float* __restrict__ x, size_t n)
{
    float s = 0.0f, s2 = 0.0f;
    const size_t stride = (size_t)gridDim.x * blockDim.x;
    for (size_t idx = (size_t)blockIdx.x * blockDim.x + threadIdx.x; idx < n; idx += stride) {
        const float vv = x[idx];
        s += vv;
        s2 += vv * vv;
    }
#pragma unroll
    for (int o = 16; o > 0; o >>= 1) {
        s += __shfl_down_sync(0xFFFFFFFFu, s, o);
        s2 += __shfl_down_sync(0xFFFFFFFFu, s2, o);
    }
    __shared__ double sh[2][8];
    const int w = threadIdx.x >> 5, l = threadIdx.x & 31;
    if (l == 0) { sh[0][w] = (double)s; sh[1][w] = (double)s2; }
    __syncthreads();
    if (threadIdx.x == 0) {
        double a = 0.0, b = 0.0;
#pragma unroll
        for (int i = 0; i < 8; i++) { a += sh[0][i]; b += sh[1][i]; }
        g_part[blockIdx.x][0] = a;
        g_part[blockIdx.x][1] = b;
    }
}

__global__ void __launch_bounds__(256) red2_kernel(int nb)
{
    double a = 0.0, b = 0.0;
    for (int i = threadIdx.x; i < nb; i += 256) { a += g_part[i][0]; b += g_part[i][1]; }
    __shared__ double sa[256], sb[256];
    sa[threadIdx.x] = a;
    sb[threadIdx.x] = b;
    __syncthreads();
    for (int o = 128; o > 0; o >>= 1) {
        if (threadIdx.x < o) { sa[threadIdx.x] += sa[threadIdx.x + o]; sb[threadIdx.x] += sb[threadIdx.x + o]; }
        __syncthreads();
    }
    if (threadIdx.x == 0) { g_red[0] = sa[0]; g_red[1] = sb[0]; }
}

// OUTK: 0 = fp32 only, 2 = also emit fp16
template <int OUTK>
__global__ void __launch_bounds__(256) norm_kernel(
    const float* __restrict__ x, const float* __restrict__ alpha,
    const float* __restrict__ beta, const float* __restrict__ eps,
    float* __restrict__ y, __half* __restrict__ yh, size_t n)
{
    const double Md = (double)n;
    const double mean = g_red[0] / Md;
    const double var = (g_red[1] - Md * mean * mean) / (Md - 1.0);
    const float sd = (float)sqrt(var);

    const size_t n4 = n >> 2;
    const size_t stride = (size_t)gridDim.x * blockDim.x;
    for (size_t i4 = (size_t)blockIdx.x * blockDim.x + threadIdx.x; i4 < n4; i4 += stride) {
        float4 v = ((const float4*)x)[i4];
        const int d = (int)((i4 * 4) & (DD - 1));
        v.x = v.x / (sd + eps[d + 0]) * alpha[d + 0] + beta[d + 0];
        v.y = v.y / (sd + eps[d + 1]) * alpha[d + 1] + beta[d + 1];
        v.z = v.z / (sd + eps[d + 2]) * alpha[d + 2] + beta[d + 2];
        v.w = v.w / (sd + eps[d + 3]) * alpha[d + 3] + beta[d + 3];
        ((float4*)y)[i4] = v;
        if (OUTK == 2) {
            ((__half2*)yh)[i4 * 2 + 0] = __floats2half2_rn(v.x, v.y);
            ((__half2*)yh)[i4 * 2 + 1] = __floats2half2_rn(v.z, v.w);
        }
    }
}

// ===================== launch =====================
extern "C" void kernel_launch(void* const* d_in, const int* in_sizes, int n_in,
                              void* d_out, int out_size)
{
    const float* x    = (const float*)d_in[0];
    const float* wq_w = (const float*)d_in[1];
    const float* wq_b = (const float*)d_in[2];
    const float* wk_w = (const float*)d_in[3];
    const float* wk_b = (const float*)d_in[4];
    const float* wv_w = (const float*)d_in[5];
    const float* wv_b = (const float*)d_in[6];
    const float* wo_w = (const float*)d_in[7];
    const float* wo_b = (const float*)d_in[8];
    const float* w1   = (const float*)d_in[9];
    const float* b1   = (const float*)d_in[10];
    const float* w2   = (const float*)d_in[11];
    const float* b2   = (const float*)d_in[12];
    const float* an_a = (const float*)d_in[13];
    const float* an_b = (const float*)d_in[14];
    const float* an_e = (const float*)d_in[15];
    const float* mn_a = (const float*)d_in[16];
    const float* mn_b = (const float*)d_in[17];
    const float* mn_e = (const float*)d_in[18];
    float* out = (float*)d_out;

    float *q, *k, *v, *attn, *out1, *Gpart, *Wt;
    cudaGetSymbolAddress((void**)&q, g_q);
    cudaGetSymbolAddress((void**)&k, g_k);
    cudaGetSymbolAddress((void**)&v, g_v);
    cudaGetSymbolAddress((void**)&attn, g_attn);
    cudaGetSymbolAddress((void**)&out1, g_out1);
    cudaGetSymbolAddress((void**)&Gpart, g_Gpart);
    cudaGetSymbolAddress((void**)&Wt, g_Wt);

    __nv_bfloat16 *xhi, *xlo, *aphi, *aplo;
    __nv_bfloat16 *wqh, *wql, *wkh, *wkl, *wvh, *wvl, *woh, *wol;
    cudaGetSymbolAddress((void**)&xhi, g_xhi);   cudaGetSymbolAddress((void**)&xlo, g_xlo);
    cudaGetSymbolAddress((void**)&aphi, g_aphi); cudaGetSymbolAddress((void**)&aplo, g_aplo);
    cudaGetSymbolAddress((void**)&wqh, g_wqhi);  cudaGetSymbolAddress((void**)&wql, g_wqlo);
    cudaGetSymbolAddress((void**)&wkh, g_wkhi);  cudaGetSymbolAddress((void**)&wkl, g_wklo);
    cudaGetSymbolAddress((void**)&wvh, g_wvhi);  cudaGetSymbolAddress((void**)&wvl, g_wvlo);
    cudaGetSymbolAddress((void**)&woh, g_wohi);  cudaGetSymbolAddress((void**)&wol, g_wolo);

    __half *w1f, *w2f, *atf, *hf;
    cudaGetSymbolAddress((void**)&w1f, g_w1f);
    cudaGetSymbolAddress((void**)&w2f, g_w2f);
    cudaGetSymbolAddress((void**)&atf, g_atf);
    cudaGetSymbolAddress((void**)&hf, g_hf);

    cudaFuncSetAttribute(gemm_mma<false, false, 0>, cudaFuncAttributeMaxDynamicSharedMemorySize, GW_SMEM);
    cudaFuncSetAttribute(gemm_mma<true,  false, 0>, cudaFuncAttributeMaxDynamicSharedMemorySize, GW_SMEM);
    cudaFuncSetAttribute(gemm_f16<false, true,  true >, cudaFuncAttributeMaxDynamicSharedMemorySize, F16_SMEM);
    cudaFuncSetAttribute(gemm_f16<true,  false, false>, cudaFuncAttributeMaxDynamicSharedMemorySize, F16_SMEM);

    // ---- convert inputs ----
    split_kernel<<<1024, 256>>>(x, xhi, xlo, TOT / 4);
    split_kernel<<<512, 256>>>(wq_w, wqh, wql, (size_t)DD * DD / 4);
    split_kernel<<<512, 256>>>(wk_w, wkh, wkl, (size_t)DD * DD / 4);
    split_kernel<<<512, 256>>>(wv_w, wvh, wvl, (size_t)DD * DD / 4);
    split_kernel<<<512, 256>>>(wo_w, woh, wol, (size_t)DD * DD / 4);
    cvtf16_kernel<<<1024, 256>>>(w1, w1f, (size_t)FF * DD / 4);
    cvtf16_kernel<<<1024, 256>>>(w2, w2f, (size_t)DD * FF / 4);

    const dim3 gProj(DD / GW_BN, MM / GW_BM);   // (8, 128)
    const dim3 gMlp1(FF / GW_BN, MM / GW_BM);   // (32, 128)

    // ---- Q/K/V projections (bf16-3) ----
    gemm_mma<false, false, 0><<<gProj, 256, GW_SMEM>>>(xhi, xlo, wqh, wql, wq_b, nullptr, q, nullptr, nullptr, MM, DD, DD);
    gemm_mma<false, false, 0><<<gProj, 256, GW_SMEM>>>(xhi, xlo, wkh, wkl, wk_b, nullptr, k, nullptr, nullptr, MM, DD, DD);
    gemm_mma<false, false, 0><<<gProj, 256, GW_SMEM>>>(xhi, xlo, wvh, wvl, wv_b, nullptr, v, nullptr, nullptr, MM, DD, DD);

    // ---- FFT attention (collapsed form) ----
    gram_kernel<<<dim3(BB * HH, 8), 256>>>(q, k, Gpart);
    weights_kernel<<<BB * HH, 256>>>(Gpart, Wt);
    applyw_kernel<<<dim3(BB * HH, NN / 64), 256>>>(v, Wt, aphi, aplo);

    // ---- output projection + residual (bf16-3) ----
    gemm_mma<true, false, 0><<<gProj, 256, GW_SMEM>>>(aphi, aplo, woh, wol, wo_b, x, attn, nullptr, nullptr, MM, DD, DD);

    // ---- rmsnorm 1 (global std), also emits fp16 for MLP1 ----
    red1_kernel<<<2048, 256>>>(attn, TOT);
    red2_kernel<<<1, 256>>>(2048);
    norm_kernel<2><<<2048, 256>>>(attn, an_a, an_b, an_e, attn, atf, TOT);

    // ---- MLP (fp16 single-product) ----
    gemm_f16<false, true, true><<<gMlp1, 256, F16_SMEM>>>(atf, w1f, b1, nullptr, nullptr, hf, MM, FF, DD);
    gemm_f16<true, false, false><<<gProj, 256, F16_SMEM>>>(hf, w2f, b2, attn, out1, nullptr, MM, DD, FF);

    // ---- rmsnorm 2 -> final output ----
    red1_kernel<<<2048, 256>>>(out1, TOT);
    red2_kernel<<<1, 256>>>(2048);
    norm_kernel<0><<<2048, 256>>>(out1, mn_a, mn_b, mn_e, out, nullptr, TOT);
}